// round 9
// baseline (speedup 1.0000x reference)
#include <cuda_runtime.h>
#include <mma.h>
#include <math.h>

using namespace nvcuda;

#define N_MAX 50000
#define N_PAD 50048
#define DEG_PAD 50176          // 49 * 1024
#define E_MAX 800000
#define HD 128
#define NEG 0.2f

// ---------------- device scratch (no runtime allocation allowed) -------------
__device__ __align__(16) float g_h  [N_PAD*HD];
__device__ __align__(16) float g_xlA[N_PAD*HD];
__device__ __align__(16) float g_xrA[N_PAD*HD];
__device__ __align__(16) float g_xlB[N_PAD*HD];
__device__ __align__(16) float g_xrB[N_PAD*HD];
__device__ __align__(16) int   g_deg[DEG_PAD];
__device__ __align__(16) int   g_rowptr[DEG_PAD+4];
__device__ __align__(16) int   g_cursor[DEG_PAD];
__device__ int   g_eidx[E_MAX+N_MAX];
__device__ int   g_esrc[E_MAX+N_MAX];
__device__ __align__(16) float g_eacsr[(E_MAX+N_MAX)*4];
__device__ __align__(16) float g_eamean[4];
__device__ float g_partial[512*4];
__device__ int   g_blk[64];

// ---------------- mean(edge_attr) + deg init (fused) -------------------------
__global__ void ea_stage1(const float* __restrict__ ea, int ne, int n) {
    int gid = blockIdx.x*blockDim.x + threadIdx.x;
    if (gid < DEG_PAD) g_deg[gid] = (gid < n) ? 1 : 0;
    float s0=0.f,s1=0.f,s2=0.f,s3=0.f;
    for (int e = gid; e < ne; e += gridDim.x*blockDim.x) {
        float4 v = *(const float4*)(ea + 4*e);
        s0+=v.x; s1+=v.y; s2+=v.z; s3+=v.w;
    }
    #pragma unroll
    for (int o=16;o>0;o>>=1){
        s0+=__shfl_xor_sync(0xffffffffu,s0,o);
        s1+=__shfl_xor_sync(0xffffffffu,s1,o);
        s2+=__shfl_xor_sync(0xffffffffu,s2,o);
        s3+=__shfl_xor_sync(0xffffffffu,s3,o);
    }
    __shared__ float sh[8][4];
    int w = threadIdx.x>>5, l = threadIdx.x&31;
    if (l==0){ sh[w][0]=s0; sh[w][1]=s1; sh[w][2]=s2; sh[w][3]=s3; }
    __syncthreads();
    if (threadIdx.x < 4){
        float t=0.f;
        #pragma unroll
        for (int i=0;i<8;i++) t+=sh[i][threadIdx.x];
        g_partial[blockIdx.x*4+threadIdx.x]=t;
    }
}

__global__ void mid_k(float invE, int nblk){
    __shared__ float sh[256];
    int t=threadIdx.x, c=t&3;
    float s=0.f;
    for (int r=t>>2; r<512; r+=64) s+=g_partial[r*4+c];
    sh[t]=s; __syncthreads();
    for (int o=128;o>=4;o>>=1){ if(t<o) sh[t]+=sh[t+o]; __syncthreads(); }
    if (t<4) g_eamean[t]=sh[t]*invE;
    __syncthreads();
    __shared__ int ws[2];
    if (t < 64){
        int lane=t&31, w=t>>5;
        int v = (t<nblk)? g_blk[t] : 0;
        int x = v;
        #pragma unroll
        for (int o=1;o<32;o<<=1){ int y=__shfl_up_sync(0xffffffffu,x,o); if(lane>=o) x+=y; }
        if (lane==31) ws[w]=x;
    }
    __syncthreads();
    if (t < 64){
        int lane=t&31, w=t>>5;
        int v = (t<nblk)? g_blk[t] : 0;
        int x = v;
        #pragma unroll
        for (int o=1;o<32;o<<=1){ int y=__shfl_up_sync(0xffffffffu,x,o); if(lane>=o) x+=y; }
        if (w==1) x += ws[0];
        if (t<nblk) g_blk[t] = x - v;
    }
}

// ---------------- CSR build ---------------------------------------------------
__global__ void deg_hist(const int* __restrict__ dsts, int ne){
    int i = (blockIdx.x*blockDim.x+threadIdx.x)*4;
    if (i+3 < ne){
        int4 d = *(const int4*)&dsts[i];
        atomicAdd(&g_deg[d.x],1); atomicAdd(&g_deg[d.y],1);
        atomicAdd(&g_deg[d.z],1); atomicAdd(&g_deg[d.w],1);
    } else {
        for (int k=i; k<ne; ++k) atomicAdd(&g_deg[dsts[k]],1);
    }
}

__global__ void scan1_k(){
    __shared__ int wsum[8];
    int t=threadIdx.x, lane=t&31, wid=t>>5;
    int i0 = blockIdx.x*1024 + t*4;
    int4 v = *(const int4*)&g_deg[i0];
    int s = v.x+v.y+v.z+v.w;
    int x = s;
    #pragma unroll
    for (int o=1;o<32;o<<=1){ int y=__shfl_up_sync(0xffffffffu,x,o); if(lane>=o) x+=y; }
    if (lane==31) wsum[wid]=x;
    __syncthreads();
    if (t==0){
        int r=0;
        #pragma unroll
        for (int i=0;i<8;i++){ int tv=wsum[i]; wsum[i]=r; r+=tv; }
        g_blk[blockIdx.x]=r;
    }
    __syncthreads();
    int ex = wsum[wid] + x - s;
    int4 rp; rp.x=ex; rp.y=ex+v.x; rp.z=rp.y+v.y; rp.w=rp.z+v.z;
    *(int4*)&g_rowptr[i0]=rp;
}

__global__ void scan3_k(){
    int off = g_blk[blockIdx.x];
    int i0 = blockIdx.x*1024 + threadIdx.x*4;
    int4 rp = *(const int4*)&g_rowptr[i0];
    rp.x+=off; rp.y+=off; rp.z+=off; rp.w+=off;
    *(int4*)&g_rowptr[i0]=rp;
    *(int4*)&g_cursor[i0]=rp;
}

__global__ void scatter_k(const int* __restrict__ srcs, const int* __restrict__ dsts,
                          const float* __restrict__ edge_attr, int ne, int n){
    int e = blockIdx.x*blockDim.x+threadIdx.x;
    if (e>=ne+n) return;
    int d, s; float4 ea;
    if (e<ne){ d = dsts[e]; s = srcs[e]; ea = *(const float4*)&edge_attr[(size_t)e*4]; }
    else     { d = s = e-ne; ea = *(const float4*)g_eamean; }
    int pos = atomicAdd(&g_cursor[d],1);
    g_eidx[pos]=e;
    g_esrc[pos]=s;
    *(float4*)&g_eacsr[(size_t)pos*4] = ea;
}

// ---------------- tf32 tensor-core GEMM: C1 = A@W1, C2 = A@W2 ----------------
#define BS_STRIDE 268
template<int ENC>
__global__ __launch_bounds__(256,1)
void gemm2_k(const float* __restrict__ A_or_x,
             const float* __restrict__ Wj, const float* __restrict__ bj,
             const float* __restrict__ Wrt, const float* __restrict__ brt,
             const float* __restrict__ W1, const float* __restrict__ W2,
             float* __restrict__ C1, float* __restrict__ C2, int n, int rowoff)
{
    extern __shared__ float dsm[];
    float (*As)[132]       = (float(*)[132])dsm;
    float (*Bs)[BS_STRIDE] = (float(*)[BS_STRIDE])(dsm + 128*132);
    __shared__ float sx[128][4];
    int t = threadIdx.x;
    int rowbase = rowoff + blockIdx.x*128;

    #pragma unroll
    for (int u=0; u<32; u++){
        int id = t + u*256;
        int mat = id>>12;
        int rem = id&4095;
        int kk = rem>>5, c4 = (rem&31)<<2;
        const float* W = mat ? W2 : W1;
        float4 v = *(const float4*)&W[(size_t)kk*HD + c4];
        float4 cv;
        cv.x = wmma::__float_to_tf32(v.x); cv.y = wmma::__float_to_tf32(v.y);
        cv.z = wmma::__float_to_tf32(v.z); cv.w = wmma::__float_to_tf32(v.w);
        *(float4*)&Bs[kk][mat*132 + c4] = cv;
    }

    if (ENC){
        for (int u=t; u<384; u+=256){
            int rr=u/3, c=u%3; int gr=rowbase+rr;
            sx[rr][c] = (gr<n)? A_or_x[gr*3+c] : 0.f;
        }
        __syncthreads();
        int k  = t & 127;
        int r0 = t >> 7;
        float wj0=Wj[k],  wj1=Wj[HD+k],  wj2=Wj[2*HD+k],  bj_=bj[k];
        float wr0=Wrt[k], wr1=Wrt[HD+k], wr2=Wrt[2*HD+k], br_=brt[k];
        int half = n>>1;
        #pragma unroll 8
        for (int i=0;i<64;i++){
            int r = r0 + 2*i;
            int gr = rowbase + r;
            float x0=sx[r][0], x1=sx[r][1], x2=sx[r][2];
            float vj = bj_ + x0*wj0 + x1*wj1 + x2*wj2;
            float vr = br_ + x0*wr0 + x1*wr1 + x2*wr2;
            float v  = (gr < half) ? vj : vr;
            v = (gr < n) ? fmaxf(v, 0.f) : 0.f;
            As[r][k] = wmma::__float_to_tf32(v);
        }
    } else {
        #pragma unroll
        for (int u=0; u<16; u++){
            int id = t + u*256;
            int r = id>>5, c4 = (id&31)<<2;
            float4 v = *(const float4*)&A_or_x[(size_t)(rowbase+r)*HD + c4];
            float4 cv;
            cv.x = wmma::__float_to_tf32(v.x); cv.y = wmma::__float_to_tf32(v.y);
            cv.z = wmma::__float_to_tf32(v.z); cv.w = wmma::__float_to_tf32(v.w);
            *(float4*)&As[r][c4] = cv;
        }
    }
    __syncthreads();

    int wid = t>>5;
    int wr  = wid&1;
    int wc  = wid>>1;
    int bcol = (wc>>1)*132 + (wc&1)*64;

    wmma::fragment<wmma::accumulator,16,16,8,float> c[4][4];
    #pragma unroll
    for (int i=0;i<4;i++)
        #pragma unroll
        for (int j=0;j<4;j++) wmma::fill_fragment(c[i][j], 0.f);

    #pragma unroll
    for (int ks=0; ks<16; ks++){
        int k0 = ks*8;
        wmma::fragment<wmma::matrix_a,16,16,8,wmma::precision::tf32,wmma::row_major> a[4];
        wmma::fragment<wmma::matrix_b,16,16,8,wmma::precision::tf32,wmma::row_major> b[4];
        #pragma unroll
        for (int i=0;i<4;i++)
            wmma::load_matrix_sync(a[i], &As[wr*64 + i*16][k0], 132);
        #pragma unroll
        for (int j=0;j<4;j++)
            wmma::load_matrix_sync(b[j], &Bs[k0][bcol + j*16], BS_STRIDE);
        #pragma unroll
        for (int i=0;i<4;i++)
            #pragma unroll
            for (int j=0;j<4;j++)
                wmma::mma_sync(c[i][j], a[i], b[j], c[i][j]);
    }

    float* Cm = (wc>>1) ? C2 : C1;
    int colbase = (wc&1)*64;
    #pragma unroll
    for (int i=0;i<4;i++)
        #pragma unroll
        for (int j=0;j<4;j++)
            wmma::store_matrix_sync(
                &Cm[(size_t)(rowbase + wr*64 + i*16)*HD + colbase + j*16],
                c[i][j], HD, wmma::mem_row_major);
}

// -------- GATv2 aggregation: warp per node, coalesced CSR payloads, 4-wide ---
__device__ __forceinline__ float edge_partial(
    float4 xl, float4 xr, float4 ea,
    float4 w0, float4 w1, float4 w2, float4 w3, float4 at)
{
    float mx = xl.x + xr.x + ea.x*w0.x + ea.y*w1.x + ea.z*w2.x + ea.w*w3.x;
    float my = xl.y + xr.y + ea.x*w0.y + ea.y*w1.y + ea.z*w2.y + ea.w*w3.y;
    float mz = xl.z + xr.z + ea.x*w0.z + ea.y*w1.z + ea.z*w2.z + ea.w*w3.z;
    float mw = xl.w + xr.w + ea.x*w0.w + ea.y*w1.w + ea.z*w2.w + ea.w*w3.w;
    float lx = mx>0.f? mx : NEG*mx;
    float ly = my>0.f? my : NEG*my;
    float lz = mz>0.f? mz : NEG*mz;
    float lw = mw>0.f? mw : NEG*mw;
    return at.x*lx + at.y*ly + at.z*lz + at.w*lw;
}

__global__ void gat_agg_k(const float* __restrict__ xl_buf,
                          const float* __restrict__ xr_buf,
                          const float* __restrict__ We,
                          const float* __restrict__ att,
                          const float* __restrict__ bias,
                          int node0, int nend){
    __shared__ __align__(16) float sWe[4*128];
    __shared__ __align__(16) float sAtt[128];
    __shared__ __align__(16) float sB[128];
    __shared__ int    sS[8][32];
    __shared__ float4 sEA[8][32];
    int t=threadIdx.x;
    for (int u=t; u<512; u+=256) sWe[u]=We[u];
    if (t<128){ sAtt[t]=att[t]; sB[t]=bias[t]; }
    __syncthreads();
    int lane = t&31, w = t>>5;
    int node = node0 + blockIdx.x*8 + w;
    if (node>=nend) return;
    int l4 = lane*4;
    float4 xr4 = *(const float4*)&xr_buf[(size_t)node*HD + l4];
    float4 at4 = *(const float4*)&sAtt[l4];
    float4 b4  = *(const float4*)&sB[l4];
    float4 w0 = *(const float4*)&sWe[0*HD + l4];
    float4 w1 = *(const float4*)&sWe[1*HD + l4];
    float4 w2 = *(const float4*)&sWe[2*HD + l4];
    float4 w3 = *(const float4*)&sWe[3*HD + l4];
    float m_run = -INFINITY, s_run = 0.f;
    float4 acc = make_float4(0.f,0.f,0.f,0.f);
    int beg = g_rowptr[node], end = g_rowptr[node+1];

    for (int base=beg; base<end; base+=32){
        int cnt = min(32, end-base);
        {
            int s = 0; float4 ea = make_float4(0.f,0.f,0.f,0.f);
            if (lane < cnt){
                s  = g_esrc[base+lane];
                ea = *(const float4*)&g_eacsr[(size_t)(base+lane)*4];
            }
            sS[w][lane] = s; sEA[w][lane] = ea;
        }
        __syncwarp();
        int j = 0;
        for (; j+4<=cnt; j+=4){
            float4 xv[4]; float p[4];
            #pragma unroll
            for (int q=0;q<4;q++)
                xv[q] = *(const float4*)&xl_buf[(size_t)sS[w][j+q]*HD + l4];
            #pragma unroll
            for (int q=0;q<4;q++)
                p[q] = edge_partial(xv[q], xr4, sEA[w][j+q], w0,w1,w2,w3, at4);
            #pragma unroll
            for (int o=16;o>0;o>>=1){
                #pragma unroll
                for (int q=0;q<4;q++) p[q] += __shfl_xor_sync(0xffffffffu, p[q], o);
            }
            #pragma unroll
            for (int q=0;q<4;q++){
                float nm = fmaxf(m_run, p[q]);
                float sc = __expf(m_run - nm);
                float wv = __expf(p[q] - nm);
                s_run = s_run*sc + wv;
                acc.x = acc.x*sc + wv*xv[q].x; acc.y = acc.y*sc + wv*xv[q].y;
                acc.z = acc.z*sc + wv*xv[q].z; acc.w = acc.w*sc + wv*xv[q].w;
                m_run = nm;
            }
        }
        for (; j<cnt; ++j){
            float4 xa = *(const float4*)&xl_buf[(size_t)sS[w][j]*HD + l4];
            float pa = edge_partial(xa, xr4, sEA[w][j], w0,w1,w2,w3, at4);
            #pragma unroll
            for (int o=16;o>0;o>>=1) pa += __shfl_xor_sync(0xffffffffu, pa, o);
            float nm = fmaxf(m_run, pa);
            float sc = __expf(m_run - nm);
            float wv = __expf(pa - nm);
            s_run = s_run*sc + wv;
            acc.x = acc.x*sc + wv*xa.x; acc.y = acc.y*sc + wv*xa.y;
            acc.z = acc.z*sc + wv*xa.z; acc.w = acc.w*sc + wv*xa.w;
            m_run = nm;
        }
        __syncwarp();
    }
    float inv = 1.f/(s_run + 1e-16f);
    float4 o;
    o.x = fmaxf(acc.x*inv + b4.x, 0.f);
    o.y = fmaxf(acc.y*inv + b4.y, 0.f);
    o.z = fmaxf(acc.z*inv + b4.z, 0.f);
    o.w = fmaxf(acc.w*inv + b4.w, 0.f);
    *(float4*)&g_h[(size_t)node*HD + l4] = o;
}

// -------- final edge scorer: CSR-ordered, warp per dst node, 4-wide -----------
__global__ void edge_score_csr(const float* __restrict__ xl_buf,
                               const float* __restrict__ xr_buf,
                               const float* __restrict__ Ws1c, const float* __restrict__ bs1,
                               const float* __restrict__ Ws2, const float* __restrict__ bs2,
                               float* __restrict__ out, int n, int ne){
    __shared__ __align__(16) float sWc[4*128];
    __shared__ __align__(16) float sB1[128];
    __shared__ __align__(16) float sW2[128];
    __shared__ int    sS[8][32];
    __shared__ int    sE[8][32];
    __shared__ float4 sEA[8][32];
    int t=threadIdx.x;
    for (int u=t;u<512;u+=256) sWc[u]=Ws1c[u];
    if (t<128){ sB1[t]=bs1[t]; sW2[t]=Ws2[t]; }
    __syncthreads();
    int lane=t&31, w=t>>5;
    int node = blockIdx.x*8 + w;
    if (node>=n) return;
    int l4=lane*4;
    float4 b  = *(const float4*)&xr_buf[(size_t)node*HD+l4];
    float4 w0=*(const float4*)&sWc[0*HD+l4];
    float4 w1=*(const float4*)&sWc[1*HD+l4];
    float4 w2=*(const float4*)&sWc[2*HD+l4];
    float4 w3=*(const float4*)&sWc[3*HD+l4];
    float4 bb=*(const float4*)&sB1[l4];
    float4 wo=*(const float4*)&sW2[l4];
    float b2 = bs2[0];
    int beg = g_rowptr[node], end = g_rowptr[node+1];

    for (int base=beg; base<end; base+=32){
        int cnt = min(32, end-base);
        {
            int s=0, eid=ne; float4 ea = make_float4(0.f,0.f,0.f,0.f);
            if (lane<cnt){
                eid = g_eidx[base+lane];
                s   = g_esrc[base+lane];
                ea  = *(const float4*)&g_eacsr[(size_t)(base+lane)*4];
            }
            sS[w][lane]=s; sE[w][lane]=eid; sEA[w][lane]=ea;
        }
        __syncwarp();
        int j=0;
        for (; j+4<=cnt; j+=4){
            float p[4];
            #pragma unroll
            for (int q=0;q<4;q++){
                float4 aa = *(const float4*)&xl_buf[(size_t)sS[w][j+q]*HD+l4];
                float4 ea = sEA[w][j+q];
                float hx = fmaxf(aa.x+b.x+ea.x*w0.x+ea.y*w1.x+ea.z*w2.x+ea.w*w3.x+bb.x, 0.f);
                float hy = fmaxf(aa.y+b.y+ea.x*w0.y+ea.y*w1.y+ea.z*w2.y+ea.w*w3.y+bb.y, 0.f);
                float hz = fmaxf(aa.z+b.z+ea.x*w0.z+ea.y*w1.z+ea.z*w2.z+ea.w*w3.z+bb.z, 0.f);
                float hw = fmaxf(aa.w+b.w+ea.x*w0.w+ea.y*w1.w+ea.z*w2.w+ea.w*w3.w+bb.w, 0.f);
                p[q] = hx*wo.x + hy*wo.y + hz*wo.z + hw*wo.w;
            }
            #pragma unroll
            for (int o=16;o>0;o>>=1){
                #pragma unroll
                for (int q=0;q<4;q++) p[q] += __shfl_xor_sync(0xffffffffu, p[q], o);
            }
            if (lane==0){
                #pragma unroll
                for (int q=0;q<4;q++){
                    int eid = sE[w][j+q];
                    if (eid<ne) out[eid] = p[q] + b2;
                }
            }
        }
        for (; j<cnt; ++j){
            float4 aa = *(const float4*)&xl_buf[(size_t)sS[w][j]*HD+l4];
            float4 ea = sEA[w][j];
            float hx = fmaxf(aa.x+b.x+ea.x*w0.x+ea.y*w1.x+ea.z*w2.x+ea.w*w3.x+bb.x, 0.f);
            float hy = fmaxf(aa.y+b.y+ea.x*w0.y+ea.y*w1.y+ea.z*w2.y+ea.w*w3.y+bb.y, 0.f);
            float hz = fmaxf(aa.z+b.z+ea.x*w0.z+ea.y*w1.z+ea.z*w2.z+ea.w*w3.z+bb.z, 0.f);
            float hw = fmaxf(aa.w+b.w+ea.x*w0.w+ea.y*w1.w+ea.z*w2.w+ea.w*w3.w+bb.w, 0.f);
            float pa = hx*wo.x + hy*wo.y + hz*wo.z + hw*wo.w;
            #pragma unroll
            for (int o=16;o>0;o>>=1) pa += __shfl_xor_sync(0xffffffffu, pa, o);
            int eid = sE[w][j];
            if (lane==0 && eid<ne) out[eid] = pa + b2;
        }
        __syncwarp();
    }
}

// -----------------------------------------------------------------------------
extern "C" void kernel_launch(void* const* d_in, const int* in_sizes, int n_in,
                              void* d_out, int out_size) {
    const float* x        = (const float*)d_in[0];
    const float* edge_attr= (const float*)d_in[1];
    const float* Wj   = (const float*)d_in[2];
    const float* bj   = (const float*)d_in[3];
    const float* Wrt  = (const float*)d_in[4];
    const float* brt  = (const float*)d_in[5];
    const float* c1_Wl  = (const float*)d_in[6];
    const float* c1_Wr  = (const float*)d_in[7];
    const float* c1_We  = (const float*)d_in[8];
    const float* c1_att = (const float*)d_in[9];
    const float* c1_b   = (const float*)d_in[10];
    const float* c2_Wl  = (const float*)d_in[11];
    const float* c2_Wr  = (const float*)d_in[12];
    const float* c2_We  = (const float*)d_in[13];
    const float* c2_att = (const float*)d_in[14];
    const float* c2_b   = (const float*)d_in[15];
    const float* Ws1  = (const float*)d_in[16];
    const float* bs1  = (const float*)d_in[17];
    const float* Ws2  = (const float*)d_in[18];
    const float* bs2  = (const float*)d_in[19];
    const int*   eidx = (const int*)d_in[20];

    int n  = in_sizes[0]/3;
    int ne = in_sizes[1]/4;
    const int* srcs = eidx;
    const int* dsts = eidx + ne;
    float* out = (float*)d_out;

    float *d_h, *d_xlA, *d_xrA, *d_xlB, *d_xrB;
    cudaGetSymbolAddress((void**)&d_h,   g_h);
    cudaGetSymbolAddress((void**)&d_xlA, g_xlA);
    cudaGetSymbolAddress((void**)&d_xrA, g_xrA);
    cudaGetSymbolAddress((void**)&d_xlB, g_xlB);
    cudaGetSymbolAddress((void**)&d_xrB, g_xrB);

    const int SMEM_GEMM = (128*132 + 128*BS_STRIDE) * 4;   // 204800 bytes
    cudaFuncSetAttribute(gemm2_k<1>, cudaFuncAttributeMaxDynamicSharedMemorySize, SMEM_GEMM);
    cudaFuncSetAttribute(gemm2_k<0>, cudaFuncAttributeMaxDynamicSharedMemorySize, SMEM_GEMM);

    int gblocks = (n+127)/128;   // 391
    int nblk = DEG_PAD/1024;     // 49

    // -------- streams + events (graph-capture fork/join pattern) --------
    const int NCH = 4;                       // row chunks for agg->gemm pipelining
    const int ROWS_PER = 98*128;             // 12544 rows per chunk (98 gemm blocks)
    cudaStream_t side = 0;
    cudaEvent_t evA=0, evB=0, evD=0, evE=0;
    cudaEvent_t ev1[NCH]={0}, ev2[NCH]={0};
    bool forked = (cudaStreamCreateWithFlags(&side, cudaStreamNonBlocking) == cudaSuccess);
    if (forked){
        if (cudaEventCreateWithFlags(&evA, cudaEventDisableTiming) != cudaSuccess) forked=false;
        if (forked && cudaEventCreateWithFlags(&evB, cudaEventDisableTiming) != cudaSuccess) forked=false;
        if (forked && cudaEventCreateWithFlags(&evD, cudaEventDisableTiming) != cudaSuccess) forked=false;
        if (forked && cudaEventCreateWithFlags(&evE, cudaEventDisableTiming) != cudaSuccess) forked=false;
        for (int c=0; forked && c<NCH; c++){
            if (cudaEventCreateWithFlags(&ev1[c], cudaEventDisableTiming) != cudaSuccess) forked=false;
            if (forked && cudaEventCreateWithFlags(&ev2[c], cudaEventDisableTiming) != cudaSuccess) forked=false;
        }
    }
    cudaStream_t sp = forked ? side : (cudaStream_t)0;

    if (forked){
        cudaEventRecord(evA, 0);
        cudaStreamWaitEvent(side, evA, 0);
    }

    // ---- side stream: CSR build (independent of GEMM1) ----
    ea_stage1<<<512,256,0,sp>>>(edge_attr, ne, n);            // launch 1
    deg_hist<<<(ne/4+255)/256,256,0,sp>>>(dsts, ne);          // launch 2
    scan1_k<<<nblk,256,0,sp>>>();                             // launch 3

    // ---- main stream: layer-1 GEMM (launch 4 <- ncu) ----
    gemm2_k<1><<<gblocks,256,SMEM_GEMM>>>(x, Wj,bj, Wrt,brt, c1_Wl, c1_Wr, d_xlA, d_xrA, n, 0);

    // ---- side stream: rest of CSR build ----
    mid_k<<<1,256,0,sp>>>(1.0f/(float)ne, nblk);
    scan3_k<<<nblk,256,0,sp>>>();
    scatter_k<<<(ne+n+255)/256,256,0,sp>>>(srcs, dsts, edge_attr, ne, n);

    if (forked){
        cudaEventRecord(evB, side);            // CSR done
        cudaStreamWaitEvent(0, evB, 0);        // agg1 needs CSR (+ gemm1, stream order)
    }

    // ---- pipeline: agg1 chunks (stream0) -> gemm2 chunks (side) ----
    // agg1 reads xlA/xrA (gathers), writes g_h rows; gemm2 chunk i reads
    // exactly g_h rows of chunk i, writes xlB/xrB. No buffer conflicts.
    for (int c=0; c<NCH; c++){
        int node0 = c*ROWS_PER;
        int nodes = (node0 < n) ? min(n - node0, ROWS_PER) : 0;
        if (nodes <= 0) break;
        gat_agg_k<<<(nodes+7)/8,256>>>(d_xlA, d_xrA, c1_We, c1_att, c1_b, node0, node0+nodes);
        int gb = (nodes+127)/128;
        if (forked){
            cudaEventRecord(ev1[c], 0);
            cudaStreamWaitEvent(side, ev1[c], 0);
        }
        gemm2_k<0><<<gb,256,SMEM_GEMM,sp>>>(d_h, Wj,bj, Wrt,brt, c2_Wl, c2_Wr, d_xlB, d_xrB, n, node0);
    }
    if (forked){
        cudaEventRecord(evD, side);            // gemm2 fully done
        cudaStreamWaitEvent(0, evD, 0);
    }

    // ---- pipeline: agg2 chunks (stream0) -> gemm3 chunks (side) ----
    // agg2 reads xlB/xrB, writes g_h; gemm3 reuses xlA/xrA as output (agg1 done).
    for (int c=0; c<NCH; c++){
        int node0 = c*ROWS_PER;
        int nodes = (node0 < n) ? min(n - node0, ROWS_PER) : 0;
        if (nodes <= 0) break;
        gat_agg_k<<<(nodes+7)/8,256>>>(d_xlB, d_xrB, c2_We, c2_att, c2_b, node0, node0+nodes);
        int gb = (nodes+127)/128;
        if (forked){
            cudaEventRecord(ev2[c], 0);
            cudaStreamWaitEvent(side, ev2[c], 0);
        }
        gemm2_k<0><<<gb,256,SMEM_GEMM,sp>>>(d_h, Wj,bj, Wrt,brt, Ws1, Ws1 + 128*HD, d_xlA, d_xrA, n, node0);
    }
    if (forked){
        cudaEventRecord(evE, side);            // gemm3 fully done
        cudaStreamWaitEvent(0, evE, 0);
    }

    // ---- final scorer (needs full gemm3 output) ----
    edge_score_csr<<<(n+7)/8,256>>>(d_xlA, d_xrA, Ws1 + 256*HD, bs1, Ws2, bs2, out, n, ne);
    // Streams/events intentionally not destroyed during capture (see R7 note).
}

// round 10
// speedup vs baseline: 1.1792x; 1.1792x over previous
#include <cuda_runtime.h>
#include <cuda_fp16.h>
#include <mma.h>
#include <math.h>

using namespace nvcuda;

#define N_MAX 50000
#define N_PAD 50048
#define DEG_PAD 50176          // 49 * 1024
#define E_MAX 800000
#define HD 128
#define NEG 0.2f

// ---------------- device scratch (no runtime allocation allowed) -------------
__device__ __align__(16) float  g_h  [N_PAD*HD];
__device__ __align__(16) __half g_xlA[N_PAD*HD];
__device__ __align__(16) __half g_xrA[N_PAD*HD];
__device__ __align__(16) __half g_xlB[N_PAD*HD];
__device__ __align__(16) __half g_xrB[N_PAD*HD];
__device__ __align__(16) int   g_deg[DEG_PAD];
__device__ __align__(16) int   g_rowptr[DEG_PAD+4];
__device__ __align__(16) int   g_cursor[DEG_PAD];
__device__ int   g_eidx[E_MAX+N_MAX];
__device__ int   g_esrc[E_MAX+N_MAX];
__device__ __align__(16) float g_eacsr[(E_MAX+N_MAX)*4];
__device__ __align__(16) float g_eamean[4];
__device__ float g_partial[512*4];
__device__ int   g_blk[64];

// half[4] -> float4 via one 8-byte load
__device__ __forceinline__ float4 ldh4(const __half* p){
    uint2 raw = *(const uint2*)p;
    __half2 h0 = *(__half2*)&raw.x;
    __half2 h1 = *(__half2*)&raw.y;
    float2 f0 = __half22float2(h0);
    float2 f1 = __half22float2(h1);
    return make_float4(f0.x, f0.y, f1.x, f1.y);
}

// ---------------- mean(edge_attr) + deg init (fused) -------------------------
__global__ void ea_stage1(const float* __restrict__ ea, int ne, int n) {
    int gid = blockIdx.x*blockDim.x + threadIdx.x;
    if (gid < DEG_PAD) g_deg[gid] = (gid < n) ? 1 : 0;
    float s0=0.f,s1=0.f,s2=0.f,s3=0.f;
    for (int e = gid; e < ne; e += gridDim.x*blockDim.x) {
        float4 v = *(const float4*)(ea + 4*e);
        s0+=v.x; s1+=v.y; s2+=v.z; s3+=v.w;
    }
    #pragma unroll
    for (int o=16;o>0;o>>=1){
        s0+=__shfl_xor_sync(0xffffffffu,s0,o);
        s1+=__shfl_xor_sync(0xffffffffu,s1,o);
        s2+=__shfl_xor_sync(0xffffffffu,s2,o);
        s3+=__shfl_xor_sync(0xffffffffu,s3,o);
    }
    __shared__ float sh[8][4];
    int w = threadIdx.x>>5, l = threadIdx.x&31;
    if (l==0){ sh[w][0]=s0; sh[w][1]=s1; sh[w][2]=s2; sh[w][3]=s3; }
    __syncthreads();
    if (threadIdx.x < 4){
        float t=0.f;
        #pragma unroll
        for (int i=0;i<8;i++) t+=sh[i][threadIdx.x];
        g_partial[blockIdx.x*4+threadIdx.x]=t;
    }
}

__global__ void mid_k(float invE, int nblk){
    __shared__ float sh[256];
    int t=threadIdx.x, c=t&3;
    float s=0.f;
    for (int r=t>>2; r<512; r+=64) s+=g_partial[r*4+c];
    sh[t]=s; __syncthreads();
    for (int o=128;o>=4;o>>=1){ if(t<o) sh[t]+=sh[t+o]; __syncthreads(); }
    if (t<4) g_eamean[t]=sh[t]*invE;
    __syncthreads();
    __shared__ int ws[2];
    if (t < 64){
        int lane=t&31, w=t>>5;
        int v = (t<nblk)? g_blk[t] : 0;
        int x = v;
        #pragma unroll
        for (int o=1;o<32;o<<=1){ int y=__shfl_up_sync(0xffffffffu,x,o); if(lane>=o) x+=y; }
        if (lane==31) ws[w]=x;
    }
    __syncthreads();
    if (t < 64){
        int lane=t&31, w=t>>5;
        int v = (t<nblk)? g_blk[t] : 0;
        int x = v;
        #pragma unroll
        for (int o=1;o<32;o<<=1){ int y=__shfl_up_sync(0xffffffffu,x,o); if(lane>=o) x+=y; }
        if (w==1) x += ws[0];
        if (t<nblk) g_blk[t] = x - v;
    }
}

// ---------------- CSR build ---------------------------------------------------
__global__ void deg_hist(const int* __restrict__ dsts, int ne){
    int i = (blockIdx.x*blockDim.x+threadIdx.x)*4;
    if (i+3 < ne){
        int4 d = *(const int4*)&dsts[i];
        atomicAdd(&g_deg[d.x],1); atomicAdd(&g_deg[d.y],1);
        atomicAdd(&g_deg[d.z],1); atomicAdd(&g_deg[d.w],1);
    } else {
        for (int k=i; k<ne; ++k) atomicAdd(&g_deg[dsts[k]],1);
    }
}

__global__ void scan1_k(){
    __shared__ int wsum[8];
    int t=threadIdx.x, lane=t&31, wid=t>>5;
    int i0 = blockIdx.x*1024 + t*4;
    int4 v = *(const int4*)&g_deg[i0];
    int s = v.x+v.y+v.z+v.w;
    int x = s;
    #pragma unroll
    for (int o=1;o<32;o<<=1){ int y=__shfl_up_sync(0xffffffffu,x,o); if(lane>=o) x+=y; }
    if (lane==31) wsum[wid]=x;
    __syncthreads();
    if (t==0){
        int r=0;
        #pragma unroll
        for (int i=0;i<8;i++){ int tv=wsum[i]; wsum[i]=r; r+=tv; }
        g_blk[blockIdx.x]=r;
    }
    __syncthreads();
    int ex = wsum[wid] + x - s;
    int4 rp; rp.x=ex; rp.y=ex+v.x; rp.z=rp.y+v.y; rp.w=rp.z+v.z;
    *(int4*)&g_rowptr[i0]=rp;
}

__global__ void scan3_k(){
    int off = g_blk[blockIdx.x];
    int i0 = blockIdx.x*1024 + threadIdx.x*4;
    int4 rp = *(const int4*)&g_rowptr[i0];
    rp.x+=off; rp.y+=off; rp.z+=off; rp.w+=off;
    *(int4*)&g_rowptr[i0]=rp;
    *(int4*)&g_cursor[i0]=rp;
}

__global__ void scatter_k(const int* __restrict__ srcs, const int* __restrict__ dsts,
                          const float* __restrict__ edge_attr, int ne, int n){
    int e = blockIdx.x*blockDim.x+threadIdx.x;
    if (e>=ne+n) return;
    int d, s; float4 ea;
    if (e<ne){ d = dsts[e]; s = srcs[e]; ea = *(const float4*)&edge_attr[(size_t)e*4]; }
    else     { d = s = e-ne; ea = *(const float4*)g_eamean; }
    int pos = atomicAdd(&g_cursor[d],1);
    g_eidx[pos]=e;
    g_esrc[pos]=s;
    *(float4*)&g_eacsr[(size_t)pos*4] = ea;
}

// ---------------- tf32 tensor-core GEMM: C1 = A@W1, C2 = A@W2 (fp16 out) -----
#define BS_STRIDE 268
template<int ENC>
__global__ __launch_bounds__(256,1)
void gemm2_k(const float* __restrict__ A_or_x,
             const float* __restrict__ Wj, const float* __restrict__ bj,
             const float* __restrict__ Wrt, const float* __restrict__ brt,
             const float* __restrict__ W1, const float* __restrict__ W2,
             __half* __restrict__ C1, __half* __restrict__ C2, int n)
{
    extern __shared__ float dsm[];
    float (*As)[132]       = (float(*)[132])dsm;
    float (*Bs)[BS_STRIDE] = (float(*)[BS_STRIDE])(dsm + 128*132);
    float (*Cs)[264]       = (float(*)[264])dsm;          // epilogue reuse
    __shared__ float sx[128][4];
    int t = threadIdx.x;
    int rowbase = blockIdx.x*128;

    #pragma unroll
    for (int u=0; u<32; u++){
        int id = t + u*256;
        int mat = id>>12;
        int rem = id&4095;
        int kk = rem>>5, c4 = (rem&31)<<2;
        const float* W = mat ? W2 : W1;
        float4 v = *(const float4*)&W[(size_t)kk*HD + c4];
        float4 cv;
        cv.x = wmma::__float_to_tf32(v.x); cv.y = wmma::__float_to_tf32(v.y);
        cv.z = wmma::__float_to_tf32(v.z); cv.w = wmma::__float_to_tf32(v.w);
        *(float4*)&Bs[kk][mat*132 + c4] = cv;
    }

    if (ENC){
        for (int u=t; u<384; u+=256){
            int rr=u/3, c=u%3; int gr=rowbase+rr;
            sx[rr][c] = (gr<n)? A_or_x[gr*3+c] : 0.f;
        }
        __syncthreads();
        int k  = t & 127;
        int r0 = t >> 7;
        float wj0=Wj[k],  wj1=Wj[HD+k],  wj2=Wj[2*HD+k],  bj_=bj[k];
        float wr0=Wrt[k], wr1=Wrt[HD+k], wr2=Wrt[2*HD+k], br_=brt[k];
        int half_ = n>>1;
        #pragma unroll 8
        for (int i=0;i<64;i++){
            int r = r0 + 2*i;
            int gr = rowbase + r;
            float x0=sx[r][0], x1=sx[r][1], x2=sx[r][2];
            float vj = bj_ + x0*wj0 + x1*wj1 + x2*wj2;
            float vr = br_ + x0*wr0 + x1*wr1 + x2*wr2;
            float v  = (gr < half_) ? vj : vr;
            v = (gr < n) ? fmaxf(v, 0.f) : 0.f;
            As[r][k] = wmma::__float_to_tf32(v);
        }
    } else {
        #pragma unroll
        for (int u=0; u<16; u++){
            int id = t + u*256;
            int r = id>>5, c4 = (id&31)<<2;
            float4 v = *(const float4*)&A_or_x[(size_t)(rowbase+r)*HD + c4];
            float4 cv;
            cv.x = wmma::__float_to_tf32(v.x); cv.y = wmma::__float_to_tf32(v.y);
            cv.z = wmma::__float_to_tf32(v.z); cv.w = wmma::__float_to_tf32(v.w);
            *(float4*)&As[r][c4] = cv;
        }
    }
    __syncthreads();

    int wid = t>>5;
    int wr  = wid&1;
    int wc  = wid>>1;
    int bcol = (wc>>1)*132 + (wc&1)*64;

    wmma::fragment<wmma::accumulator,16,16,8,float> c[4][4];
    #pragma unroll
    for (int i=0;i<4;i++)
        #pragma unroll
        for (int j=0;j<4;j++) wmma::fill_fragment(c[i][j], 0.f);

    #pragma unroll
    for (int ks=0; ks<16; ks++){
        int k0 = ks*8;
        wmma::fragment<wmma::matrix_a,16,16,8,wmma::precision::tf32,wmma::row_major> a[4];
        wmma::fragment<wmma::matrix_b,16,16,8,wmma::precision::tf32,wmma::row_major> b[4];
        #pragma unroll
        for (int i=0;i<4;i++)
            wmma::load_matrix_sync(a[i], &As[wr*64 + i*16][k0], 132);
        #pragma unroll
        for (int j=0;j<4;j++)
            wmma::load_matrix_sync(b[j], &Bs[k0][bcol + j*16], BS_STRIDE);
        #pragma unroll
        for (int i=0;i<4;i++)
            #pragma unroll
            for (int j=0;j<4;j++)
                wmma::mma_sync(c[i][j], a[i], b[j], c[i][j]);
    }

    // ---- epilogue: accums -> smem (fp32) -> fp16 global ----
    __syncthreads();   // mainloop reads of As/Bs done; reuse dsm as Cs
    #pragma unroll
    for (int i=0;i<4;i++)
        #pragma unroll
        for (int j=0;j<4;j++)
            wmma::store_matrix_sync(&Cs[wr*64 + i*16][bcol + j*16],
                                    c[i][j], 264, wmma::mem_row_major);
    __syncthreads();
    #pragma unroll
    for (int u=0; u<64; u++){
        int id = t + u*256;          // 0..16383 half2 units
        int mat = id>>13;            // 0..1
        int rem = id&8191;
        int row = rem>>6;            // 0..127
        int c2  = (rem&63)<<1;       // even col
        float v0 = Cs[row][mat*132 + c2];
        float v1 = Cs[row][mat*132 + c2 + 1];
        __half2 hv = __floats2half2_rn(v0, v1);
        __half* Cm = mat ? C2 : C1;
        *(__half2*)&Cm[(size_t)(rowbase+row)*HD + c2] = hv;
    }
}

// -------- GATv2 aggregation: warp per node, fp16 gathers, 4-wide ILP ----------
__device__ __forceinline__ float edge_partial(
    float4 xl, float4 xr, float4 ea,
    float4 w0, float4 w1, float4 w2, float4 w3, float4 at)
{
    float mx = xl.x + xr.x + ea.x*w0.x + ea.y*w1.x + ea.z*w2.x + ea.w*w3.x;
    float my = xl.y + xr.y + ea.x*w0.y + ea.y*w1.y + ea.z*w2.y + ea.w*w3.y;
    float mz = xl.z + xr.z + ea.x*w0.z + ea.y*w1.z + ea.z*w2.z + ea.w*w3.z;
    float mw = xl.w + xr.w + ea.x*w0.w + ea.y*w1.w + ea.z*w2.w + ea.w*w3.w;
    float lx = mx>0.f? mx : NEG*mx;
    float ly = my>0.f? my : NEG*my;
    float lz = mz>0.f? mz : NEG*mz;
    float lw = mw>0.f? mw : NEG*mw;
    return at.x*lx + at.y*ly + at.z*lz + at.w*lw;
}

__global__ void gat_agg_k(const __half* __restrict__ xl_buf,
                          const __half* __restrict__ xr_buf,
                          const float* __restrict__ We,
                          const float* __restrict__ att,
                          const float* __restrict__ bias,
                          int n){
    __shared__ __align__(16) float sWe[4*128];
    __shared__ __align__(16) float sAtt[128];
    __shared__ __align__(16) float sB[128];
    __shared__ int    sS[8][32];
    __shared__ float4 sEA[8][32];
    int t=threadIdx.x;
    for (int u=t; u<512; u+=256) sWe[u]=We[u];
    if (t<128){ sAtt[t]=att[t]; sB[t]=bias[t]; }
    __syncthreads();
    int lane = t&31, w = t>>5;
    int node = blockIdx.x*8 + w;
    if (node>=n) return;
    int l4 = lane*4;
    float4 xr4 = ldh4(xr_buf + (size_t)node*HD + l4);
    float4 at4 = *(const float4*)&sAtt[l4];
    float4 b4  = *(const float4*)&sB[l4];
    float4 w0 = *(const float4*)&sWe[0*HD + l4];
    float4 w1 = *(const float4*)&sWe[1*HD + l4];
    float4 w2 = *(const float4*)&sWe[2*HD + l4];
    float4 w3 = *(const float4*)&sWe[3*HD + l4];
    float m_run = -INFINITY, s_run = 0.f;
    float4 acc = make_float4(0.f,0.f,0.f,0.f);
    int beg = g_rowptr[node], end = g_rowptr[node+1];

    for (int base=beg; base<end; base+=32){
        int cnt = min(32, end-base);
        {
            int s = 0; float4 ea = make_float4(0.f,0.f,0.f,0.f);
            if (lane < cnt){
                s  = g_esrc[base+lane];
                ea = *(const float4*)&g_eacsr[(size_t)(base+lane)*4];
            }
            sS[w][lane] = s; sEA[w][lane] = ea;
        }
        __syncwarp();
        int j = 0;
        for (; j+4<=cnt; j+=4){
            float4 xv[4]; float p[4];
            #pragma unroll
            for (int q=0;q<4;q++)
                xv[q] = ldh4(xl_buf + (size_t)sS[w][j+q]*HD + l4);
            #pragma unroll
            for (int q=0;q<4;q++)
                p[q] = edge_partial(xv[q], xr4, sEA[w][j+q], w0,w1,w2,w3, at4);
            #pragma unroll
            for (int o=16;o>0;o>>=1){
                #pragma unroll
                for (int q=0;q<4;q++) p[q] += __shfl_xor_sync(0xffffffffu, p[q], o);
            }
            #pragma unroll
            for (int q=0;q<4;q++){
                float nm = fmaxf(m_run, p[q]);
                float sc = __expf(m_run - nm);
                float wv = __expf(p[q] - nm);
                s_run = s_run*sc + wv;
                acc.x = acc.x*sc + wv*xv[q].x; acc.y = acc.y*sc + wv*xv[q].y;
                acc.z = acc.z*sc + wv*xv[q].z; acc.w = acc.w*sc + wv*xv[q].w;
                m_run = nm;
            }
        }
        for (; j<cnt; ++j){
            float4 xa = ldh4(xl_buf + (size_t)sS[w][j]*HD + l4);
            float pa = edge_partial(xa, xr4, sEA[w][j], w0,w1,w2,w3, at4);
            #pragma unroll
            for (int o=16;o>0;o>>=1) pa += __shfl_xor_sync(0xffffffffu, pa, o);
            float nm = fmaxf(m_run, pa);
            float sc = __expf(m_run - nm);
            float wv = __expf(pa - nm);
            s_run = s_run*sc + wv;
            acc.x = acc.x*sc + wv*xa.x; acc.y = acc.y*sc + wv*xa.y;
            acc.z = acc.z*sc + wv*xa.z; acc.w = acc.w*sc + wv*xa.w;
            m_run = nm;
        }
        __syncwarp();
    }
    float inv = 1.f/(s_run + 1e-16f);
    float4 o;
    o.x = fmaxf(acc.x*inv + b4.x, 0.f);
    o.y = fmaxf(acc.y*inv + b4.y, 0.f);
    o.z = fmaxf(acc.z*inv + b4.z, 0.f);
    o.w = fmaxf(acc.w*inv + b4.w, 0.f);
    *(float4*)&g_h[(size_t)node*HD + l4] = o;
}

// -------- final edge scorer: CSR-ordered, warp per dst node, fp16 gathers -----
__global__ void edge_score_csr(const __half* __restrict__ xl_buf,
                               const __half* __restrict__ xr_buf,
                               const float* __restrict__ Ws1c, const float* __restrict__ bs1,
                               const float* __restrict__ Ws2, const float* __restrict__ bs2,
                               float* __restrict__ out, int n, int ne){
    __shared__ __align__(16) float sWc[4*128];
    __shared__ __align__(16) float sB1[128];
    __shared__ __align__(16) float sW2[128];
    __shared__ int    sS[8][32];
    __shared__ int    sE[8][32];
    __shared__ float4 sEA[8][32];
    int t=threadIdx.x;
    for (int u=t;u<512;u+=256) sWc[u]=Ws1c[u];
    if (t<128){ sB1[t]=bs1[t]; sW2[t]=Ws2[t]; }
    __syncthreads();
    int lane=t&31, w=t>>5;
    int node = blockIdx.x*8 + w;
    if (node>=n) return;
    int l4=lane*4;
    float4 b  = ldh4(xr_buf + (size_t)node*HD + l4);
    float4 w0=*(const float4*)&sWc[0*HD+l4];
    float4 w1=*(const float4*)&sWc[1*HD+l4];
    float4 w2=*(const float4*)&sWc[2*HD+l4];
    float4 w3=*(const float4*)&sWc[3*HD+l4];
    float4 bb=*(const float4*)&sB1[l4];
    float4 wo=*(const float4*)&sW2[l4];
    float b2 = bs2[0];
    int beg = g_rowptr[node], end = g_rowptr[node+1];

    for (int base=beg; base<end; base+=32){
        int cnt = min(32, end-base);
        {
            int s=0, eid=ne; float4 ea = make_float4(0.f,0.f,0.f,0.f);
            if (lane<cnt){
                eid = g_eidx[base+lane];
                s   = g_esrc[base+lane];
                ea  = *(const float4*)&g_eacsr[(size_t)(base+lane)*4];
            }
            sS[w][lane]=s; sE[w][lane]=eid; sEA[w][lane]=ea;
        }
        __syncwarp();
        int j=0;
        for (; j+4<=cnt; j+=4){
            float p[4];
            #pragma unroll
            for (int q=0;q<4;q++){
                float4 aa = ldh4(xl_buf + (size_t)sS[w][j+q]*HD + l4);
                float4 ea = sEA[w][j+q];
                float hx = fmaxf(aa.x+b.x+ea.x*w0.x+ea.y*w1.x+ea.z*w2.x+ea.w*w3.x+bb.x, 0.f);
                float hy = fmaxf(aa.y+b.y+ea.x*w0.y+ea.y*w1.y+ea.z*w2.y+ea.w*w3.y+bb.y, 0.f);
                float hz = fmaxf(aa.z+b.z+ea.x*w0.z+ea.y*w1.z+ea.z*w2.z+ea.w*w3.z+bb.z, 0.f);
                float hw = fmaxf(aa.w+b.w+ea.x*w0.w+ea.y*w1.w+ea.z*w2.w+ea.w*w3.w+bb.w, 0.f);
                p[q] = hx*wo.x + hy*wo.y + hz*wo.z + hw*wo.w;
            }
            #pragma unroll
            for (int o=16;o>0;o>>=1){
                #pragma unroll
                for (int q=0;q<4;q++) p[q] += __shfl_xor_sync(0xffffffffu, p[q], o);
            }
            if (lane==0){
                #pragma unroll
                for (int q=0;q<4;q++){
                    int eid = sE[w][j+q];
                    if (eid<ne) out[eid] = p[q] + b2;
                }
            }
        }
        for (; j<cnt; ++j){
            float4 aa = ldh4(xl_buf + (size_t)sS[w][j]*HD + l4);
            float4 ea = sEA[w][j];
            float hx = fmaxf(aa.x+b.x+ea.x*w0.x+ea.y*w1.x+ea.z*w2.x+ea.w*w3.x+bb.x, 0.f);
            float hy = fmaxf(aa.y+b.y+ea.x*w0.y+ea.y*w1.y+ea.z*w2.y+ea.w*w3.y+bb.y, 0.f);
            float hz = fmaxf(aa.z+b.z+ea.x*w0.z+ea.y*w1.z+ea.z*w2.z+ea.w*w3.z+bb.z, 0.f);
            float hw = fmaxf(aa.w+b.w+ea.x*w0.w+ea.y*w1.w+ea.z*w2.w+ea.w*w3.w+bb.w, 0.f);
            float pa = hx*wo.x + hy*wo.y + hz*wo.z + hw*wo.w;
            #pragma unroll
            for (int o=16;o>0;o>>=1) pa += __shfl_xor_sync(0xffffffffu, pa, o);
            int eid = sE[w][j];
            if (lane==0 && eid<ne) out[eid] = pa + b2;
        }
        __syncwarp();
    }
}

// -----------------------------------------------------------------------------
extern "C" void kernel_launch(void* const* d_in, const int* in_sizes, int n_in,
                              void* d_out, int out_size) {
    const float* x        = (const float*)d_in[0];
    const float* edge_attr= (const float*)d_in[1];
    const float* Wj   = (const float*)d_in[2];
    const float* bj   = (const float*)d_in[3];
    const float* Wrt  = (const float*)d_in[4];
    const float* brt  = (const float*)d_in[5];
    const float* c1_Wl  = (const float*)d_in[6];
    const float* c1_Wr  = (const float*)d_in[7];
    const float* c1_We  = (const float*)d_in[8];
    const float* c1_att = (const float*)d_in[9];
    const float* c1_b   = (const float*)d_in[10];
    const float* c2_Wl  = (const float*)d_in[11];
    const float* c2_Wr  = (const float*)d_in[12];
    const float* c2_We  = (const float*)d_in[13];
    const float* c2_att = (const float*)d_in[14];
    const float* c2_b   = (const float*)d_in[15];
    const float* Ws1  = (const float*)d_in[16];
    const float* bs1  = (const float*)d_in[17];
    const float* Ws2  = (const float*)d_in[18];
    const float* bs2  = (const float*)d_in[19];
    const int*   eidx = (const int*)d_in[20];

    int n  = in_sizes[0]/3;
    int ne = in_sizes[1]/4;
    const int* srcs = eidx;
    const int* dsts = eidx + ne;
    float* out = (float*)d_out;

    float *d_h;
    __half *d_xlA, *d_xrA, *d_xlB, *d_xrB;
    cudaGetSymbolAddress((void**)&d_h,   g_h);
    cudaGetSymbolAddress((void**)&d_xlA, g_xlA);
    cudaGetSymbolAddress((void**)&d_xrA, g_xrA);
    cudaGetSymbolAddress((void**)&d_xlB, g_xlB);
    cudaGetSymbolAddress((void**)&d_xrB, g_xrB);

    const int SMEM_GEMM = (128*132 + 128*BS_STRIDE) * 4;   // 204800 bytes
    cudaFuncSetAttribute(gemm2_k<1>, cudaFuncAttributeMaxDynamicSharedMemorySize, SMEM_GEMM);
    cudaFuncSetAttribute(gemm2_k<0>, cudaFuncAttributeMaxDynamicSharedMemorySize, SMEM_GEMM);

    int gblocks = (n+127)/128;   // 391
    int nblk = DEG_PAD/1024;     // 49

    // R8 fork/join: prep overlaps gemm1 (validated win)
    cudaStream_t side = 0;
    cudaEvent_t evA = 0, evB = 0;
    bool forked = (cudaStreamCreateWithFlags(&side, cudaStreamNonBlocking) == cudaSuccess);
    if (forked &&
        (cudaEventCreateWithFlags(&evA, cudaEventDisableTiming) != cudaSuccess ||
         cudaEventCreateWithFlags(&evB, cudaEventDisableTiming) != cudaSuccess)) {
        forked = false;
    }
    cudaStream_t sp = forked ? side : (cudaStream_t)0;

    if (forked){
        cudaEventRecord(evA, 0);
        cudaStreamWaitEvent(side, evA, 0);
    }

    // ---- side stream: CSR build chain ----
    ea_stage1<<<512,256,0,sp>>>(edge_attr, ne, n);            // launch 1
    deg_hist<<<(ne/4+255)/256,256,0,sp>>>(dsts, ne);          // launch 2
    scan1_k<<<nblk,256,0,sp>>>();                             // launch 3

    // ---- main stream: layer-1 GEMM (launch 4 <- ncu) ----
    gemm2_k<1><<<gblocks,256,SMEM_GEMM>>>(x, Wj,bj, Wrt,brt, c1_Wl, c1_Wr, d_xlA, d_xrA, n);

    // ---- side stream: rest of CSR build ----
    mid_k<<<1,256,0,sp>>>(1.0f/(float)ne, nblk);
    scan3_k<<<nblk,256,0,sp>>>();
    scatter_k<<<(ne+n+255)/256,256,0,sp>>>(srcs, dsts, edge_attr, ne, n);

    if (forked){
        cudaEventRecord(evB, side);
        cudaStreamWaitEvent(0, evB, 0);
    }

    // ---- main stream: rest of the network ----
    gat_agg_k<<<(n+7)/8,256>>>(d_xlA, d_xrA, c1_We, c1_att, c1_b, n);

    gemm2_k<0><<<gblocks,256,SMEM_GEMM>>>(d_h, Wj,bj, Wrt,brt, c2_Wl, c2_Wr, d_xlB, d_xrB, n);
    gat_agg_k<<<(n+7)/8,256>>>(d_xlB, d_xrB, c2_We, c2_att, c2_b, n);

    gemm2_k<0><<<gblocks,256,SMEM_GEMM>>>(d_h, Wj,bj, Wrt,brt, Ws1, Ws1 + 128*HD, d_xlA, d_xrA, n);
    edge_score_csr<<<(n+7)/8,256>>>(d_xlA, d_xrA, Ws1 + 256*HD, bs1, Ws2, bs2, out, n, ne);
    // Streams/events intentionally not destroyed during capture (see R7 note).
}

// round 12
// speedup vs baseline: 1.4915x; 1.2648x over previous
#include <cuda_runtime.h>
#include <cuda_fp16.h>
#include <mma.h>
#include <math.h>

using namespace nvcuda;

#define N_MAX 50000
#define N_PAD 50048
#define DEG_PAD 50176          // 49 * 1024
#define E_MAX 800000
#define HD 128
#define NEG 0.2f

// ---------------- device scratch (no runtime allocation allowed) -------------
__device__ __align__(16) float  g_h  [N_PAD*HD];
__device__ __align__(16) __half g_xlA[N_PAD*HD];
__device__ __align__(16) __half g_xrA[N_PAD*HD];
__device__ __align__(16) __half g_xlB[N_PAD*HD];
__device__ __align__(16) __half g_xrB[N_PAD*HD];
__device__ __align__(16) int   g_deg[DEG_PAD];
__device__ __align__(16) int   g_rowptr[DEG_PAD+4];
__device__ __align__(16) int   g_cursor[DEG_PAD];
__device__ int   g_eidx[E_MAX+N_MAX];
__device__ int   g_esrc[E_MAX+N_MAX];
__device__ __align__(16) float g_eacsr[(E_MAX+N_MAX)*4];
__device__ __align__(16) float g_eamean[4];
__device__ float g_partial[512*4];
__device__ int   g_blk[64];

// half[4] -> float4 via one 8-byte load
__device__ __forceinline__ float4 ldh4(const __half* p){
    uint2 raw = *(const uint2*)p;
    __half2 h0 = *(__half2*)&raw.x;
    __half2 h1 = *(__half2*)&raw.y;
    float2 f0 = __half22float2(h0);
    float2 f1 = __half22float2(h1);
    return make_float4(f0.x, f0.y, f1.x, f1.y);
}

// float4 -> half[4] 8-byte pack
__device__ __forceinline__ uint2 f4toh4(float4 v){
    __half2 h0 = __floats2half2_rn(v.x, v.y);
    __half2 h1 = __floats2half2_rn(v.z, v.w);
    uint2 r;
    r.x = *(unsigned*)&h0;
    r.y = *(unsigned*)&h1;
    return r;
}

// ---------------- mean(edge_attr) + deg init (fused) -------------------------
__global__ void ea_stage1(const float* __restrict__ ea, int ne, int n) {
    int gid = blockIdx.x*blockDim.x + threadIdx.x;
    if (gid < DEG_PAD) g_deg[gid] = (gid < n) ? 1 : 0;
    float s0=0.f,s1=0.f,s2=0.f,s3=0.f;
    for (int e = gid; e < ne; e += gridDim.x*blockDim.x) {
        float4 v = *(const float4*)(ea + 4*e);
        s0+=v.x; s1+=v.y; s2+=v.z; s3+=v.w;
    }
    #pragma unroll
    for (int o=16;o>0;o>>=1){
        s0+=__shfl_xor_sync(0xffffffffu,s0,o);
        s1+=__shfl_xor_sync(0xffffffffu,s1,o);
        s2+=__shfl_xor_sync(0xffffffffu,s2,o);
        s3+=__shfl_xor_sync(0xffffffffu,s3,o);
    }
    __shared__ float sh[8][4];
    int w = threadIdx.x>>5, l = threadIdx.x&31;
    if (l==0){ sh[w][0]=s0; sh[w][1]=s1; sh[w][2]=s2; sh[w][3]=s3; }
    __syncthreads();
    if (threadIdx.x < 4){
        float t=0.f;
        #pragma unroll
        for (int i=0;i<8;i++) t+=sh[i][threadIdx.x];
        g_partial[blockIdx.x*4+threadIdx.x]=t;
    }
}

__global__ void mid_k(float invE, int nblk){
    __shared__ float sh[256];
    int t=threadIdx.x, c=t&3;
    float s=0.f;
    for (int r=t>>2; r<512; r+=64) s+=g_partial[r*4+c];
    sh[t]=s; __syncthreads();
    for (int o=128;o>=4;o>>=1){ if(t<o) sh[t]+=sh[t+o]; __syncthreads(); }
    if (t<4) g_eamean[t]=sh[t]*invE;
    __syncthreads();
    __shared__ int ws[2];
    if (t < 64){
        int lane=t&31, w=t>>5;
        int v = (t<nblk)? g_blk[t] : 0;
        int x = v;
        #pragma unroll
        for (int o=1;o<32;o<<=1){ int y=__shfl_up_sync(0xffffffffu,x,o); if(lane>=o) x+=y; }
        if (lane==31) ws[w]=x;
    }
    __syncthreads();
    if (t < 64){
        int lane=t&31, w=t>>5;
        int v = (t<nblk)? g_blk[t] : 0;
        int x = v;
        #pragma unroll
        for (int o=1;o<32;o<<=1){ int y=__shfl_up_sync(0xffffffffu,x,o); if(lane>=o) x+=y; }
        if (w==1) x += ws[0];
        if (t<nblk) g_blk[t] = x - v;
    }
}

// ---------------- CSR build ---------------------------------------------------
__global__ void deg_hist(const int* __restrict__ dsts, int ne){
    int i = (blockIdx.x*blockDim.x+threadIdx.x)*4;
    if (i+3 < ne){
        int4 d = *(const int4*)&dsts[i];
        atomicAdd(&g_deg[d.x],1); atomicAdd(&g_deg[d.y],1);
        atomicAdd(&g_deg[d.z],1); atomicAdd(&g_deg[d.w],1);
    } else {
        for (int k=i; k<ne; ++k) atomicAdd(&g_deg[dsts[k]],1);
    }
}

__global__ void scan1_k(){
    __shared__ int wsum[8];
    int t=threadIdx.x, lane=t&31, wid=t>>5;
    int i0 = blockIdx.x*1024 + t*4;
    int4 v = *(const int4*)&g_deg[i0];
    int s = v.x+v.y+v.z+v.w;
    int x = s;
    #pragma unroll
    for (int o=1;o<32;o<<=1){ int y=__shfl_up_sync(0xffffffffu,x,o); if(lane>=o) x+=y; }
    if (lane==31) wsum[wid]=x;
    __syncthreads();
    if (t==0){
        int r=0;
        #pragma unroll
        for (int i=0;i<8;i++){ int tv=wsum[i]; wsum[i]=r; r+=tv; }
        g_blk[blockIdx.x]=r;
    }
    __syncthreads();
    int ex = wsum[wid] + x - s;
    int4 rp; rp.x=ex; rp.y=ex+v.x; rp.z=rp.y+v.y; rp.w=rp.z+v.z;
    *(int4*)&g_rowptr[i0]=rp;
}

__global__ void scan3_k(){
    int off = g_blk[blockIdx.x];
    int i0 = blockIdx.x*1024 + threadIdx.x*4;
    int4 rp = *(const int4*)&g_rowptr[i0];
    rp.x+=off; rp.y+=off; rp.z+=off; rp.w+=off;
    *(int4*)&g_rowptr[i0]=rp;
    *(int4*)&g_cursor[i0]=rp;
}

__global__ void scatter_k(const int* __restrict__ srcs, const int* __restrict__ dsts,
                          const float* __restrict__ edge_attr, int ne, int n){
    int e = blockIdx.x*blockDim.x+threadIdx.x;
    if (e>=ne+n) return;
    int d, s; float4 ea;
    if (e<ne){ d = dsts[e]; s = srcs[e]; ea = *(const float4*)&edge_attr[(size_t)e*4]; }
    else     { d = s = e-ne; ea = *(const float4*)g_eamean; }
    int pos = atomicAdd(&g_cursor[d],1);
    g_eidx[pos]=e;
    g_esrc[pos]=s;
    *(float4*)&g_eacsr[(size_t)pos*4] = ea;
}

// ---------------- fp16 tensor-core GEMM: C1 = A@W1, C2 = A@W2 (fp16 out) -----
// BM=128 x BN=256 (two mats). 8 warps, warp tile 64x64, K=16 per MMA (8 steps).
// A/B staged as half; fp32 accumulate; fp16 output.
#define AS_STRIDE 136          // halves
#define BSH_STRIDE 272         // halves (two 128-col mats, 136 each)
template<int ENC>
__global__ __launch_bounds__(256,1)
void gemm2_k(const float* __restrict__ A_or_x,
             const float* __restrict__ Wj, const float* __restrict__ bj,
             const float* __restrict__ Wrt, const float* __restrict__ brt,
             const float* __restrict__ W1, const float* __restrict__ W2,
             __half* __restrict__ C1, __half* __restrict__ C2, int n)
{
    extern __shared__ char dsmc[];
    __half (*As)[AS_STRIDE]  = (__half(*)[AS_STRIDE])dsmc;                    // 34816 B
    __half (*Bs)[BSH_STRIDE] = (__half(*)[BSH_STRIDE])(dsmc + 128*AS_STRIDE*2); // 69632 B
    float  (*Cs)[264]        = (float(*)[264])dsmc;                           // epilogue reuse
    __shared__ float sx[128][4];
    int t = threadIdx.x;
    int rowbase = blockIdx.x*128;

    // ---- stage both weight mats as half: 2*128*128 halves = 8192 groups of 4 ----
    #pragma unroll
    for (int u=0; u<32; u++){
        int id = t + u*256;            // 0..8191 groups of 4
        int mat = id>>12;              // 0..1 (4096 groups per mat)  [R11 FIX]
        int rem = id&4095;
        int kk = rem>>5, c4 = (rem&31)<<2;   // kk 0..127, c4 0..124
        const float* W = mat ? W2 : W1;
        float4 v = *(const float4*)&W[(size_t)kk*HD + c4];
        *(uint2*)&Bs[kk][mat*136 + c4] = f4toh4(v);
    }

    // ---- stage A tile as half ----
    if (ENC){
        for (int u=t; u<384; u+=256){
            int rr=u/3, c=u%3; int gr=rowbase+rr;
            sx[rr][c] = (gr<n)? A_or_x[gr*3+c] : 0.f;
        }
        __syncthreads();
        int k  = t & 127;
        int r0 = t >> 7;
        float wj0=Wj[k],  wj1=Wj[HD+k],  wj2=Wj[2*HD+k],  bj_=bj[k];
        float wr0=Wrt[k], wr1=Wrt[HD+k], wr2=Wrt[2*HD+k], br_=brt[k];
        int half_ = n>>1;
        #pragma unroll 8
        for (int i=0;i<64;i++){
            int r = r0 + 2*i;
            int gr = rowbase + r;
            float x0=sx[r][0], x1=sx[r][1], x2=sx[r][2];
            float vj = bj_ + x0*wj0 + x1*wj1 + x2*wj2;
            float vr = br_ + x0*wr0 + x1*wr1 + x2*wr2;
            float v  = (gr < half_) ? vj : vr;
            v = (gr < n) ? fmaxf(v, 0.f) : 0.f;
            As[r][k] = __float2half_rn(v);
        }
    } else {
        #pragma unroll
        for (int u=0; u<16; u++){
            int id = t + u*256;        // 0..4095 groups of 4
            int r = id>>5, c4 = (id&31)<<2;
            float4 v = *(const float4*)&A_or_x[(size_t)(rowbase+r)*HD + c4];
            *(uint2*)&As[r][c4] = f4toh4(v);
        }
    }
    __syncthreads();

    int wid = t>>5;
    int wr  = wid&1;                    // rows wr*64..+64
    int wc  = wid>>1;                   // cols wc*64..+64 (of 256)
    int bcol = (wc>>1)*136 + (wc&1)*64;

    wmma::fragment<wmma::accumulator,16,16,16,float> c[4][4];
    #pragma unroll
    for (int i=0;i<4;i++)
        #pragma unroll
        for (int j=0;j<4;j++) wmma::fill_fragment(c[i][j], 0.f);

    #pragma unroll
    for (int ks=0; ks<8; ks++){
        int k0 = ks*16;
        wmma::fragment<wmma::matrix_a,16,16,16,__half,wmma::row_major> a[4];
        wmma::fragment<wmma::matrix_b,16,16,16,__half,wmma::row_major> b[4];
        #pragma unroll
        for (int i=0;i<4;i++)
            wmma::load_matrix_sync(a[i], &As[wr*64 + i*16][k0], AS_STRIDE);
        #pragma unroll
        for (int j=0;j<4;j++)
            wmma::load_matrix_sync(b[j], &Bs[k0][bcol + j*16], BSH_STRIDE);
        #pragma unroll
        for (int i=0;i<4;i++)
            #pragma unroll
            for (int j=0;j<4;j++)
                wmma::mma_sync(c[i][j], a[i], b[j], c[i][j]);
    }

    // ---- epilogue: fp32 accums -> smem -> fp16 global ----
    __syncthreads();   // all As/Bs reads done; reuse dsm as Cs (fp32)
    #pragma unroll
    for (int i=0;i<4;i++)
        #pragma unroll
        for (int j=0;j<4;j++)
            wmma::store_matrix_sync(&Cs[wr*64 + i*16][(wc>>1)*132 + (wc&1)*64 + j*16],
                                    c[i][j], 264, wmma::mem_row_major);
    __syncthreads();
    #pragma unroll
    for (int u=0; u<64; u++){
        int id = t + u*256;          // 0..16383 half2 units
        int mat = id>>13;            // 0..1
        int rem = id&8191;
        int row = rem>>6;            // 0..127
        int c2  = (rem&63)<<1;       // even col
        float v0 = Cs[row][mat*132 + c2];
        float v1 = Cs[row][mat*132 + c2 + 1];
        __half2 hv = __floats2half2_rn(v0, v1);
        __half* Cm = mat ? C2 : C1;
        *(__half2*)&Cm[(size_t)(rowbase+row)*HD + c2] = hv;
    }
}

// -------- GATv2 aggregation: warp per node, fp16 gathers, 4-wide ILP ----------
__device__ __forceinline__ float edge_partial(
    float4 xl, float4 xr, float4 ea,
    float4 w0, float4 w1, float4 w2, float4 w3, float4 at)
{
    float mx = xl.x + xr.x + ea.x*w0.x + ea.y*w1.x + ea.z*w2.x + ea.w*w3.x;
    float my = xl.y + xr.y + ea.x*w0.y + ea.y*w1.y + ea.z*w2.y + ea.w*w3.y;
    float mz = xl.z + xr.z + ea.x*w0.z + ea.y*w1.z + ea.z*w2.z + ea.w*w3.z;
    float mw = xl.w + xr.w + ea.x*w0.w + ea.y*w1.w + ea.z*w2.w + ea.w*w3.w;
    float lx = mx>0.f? mx : NEG*mx;
    float ly = my>0.f? my : NEG*my;
    float lz = mz>0.f? mz : NEG*mz;
    float lw = mw>0.f? mw : NEG*mw;
    return at.x*lx + at.y*ly + at.z*lz + at.w*lw;
}

__global__ void gat_agg_k(const __half* __restrict__ xl_buf,
                          const __half* __restrict__ xr_buf,
                          const float* __restrict__ We,
                          const float* __restrict__ att,
                          const float* __restrict__ bias,
                          int n){
    __shared__ __align__(16) float sWe[4*128];
    __shared__ __align__(16) float sAtt[128];
    __shared__ __align__(16) float sB[128];
    __shared__ int    sS[8][32];
    __shared__ float4 sEA[8][32];
    int t=threadIdx.x;
    for (int u=t; u<512; u+=256) sWe[u]=We[u];
    if (t<128){ sAtt[t]=att[t]; sB[t]=bias[t]; }
    __syncthreads();
    int lane = t&31, w = t>>5;
    int node = blockIdx.x*8 + w;
    if (node>=n) return;
    int l4 = lane*4;
    float4 xr4 = ldh4(xr_buf + (size_t)node*HD + l4);
    float4 at4 = *(const float4*)&sAtt[l4];
    float4 b4  = *(const float4*)&sB[l4];
    float4 w0 = *(const float4*)&sWe[0*HD + l4];
    float4 w1 = *(const float4*)&sWe[1*HD + l4];
    float4 w2 = *(const float4*)&sWe[2*HD + l4];
    float4 w3 = *(const float4*)&sWe[3*HD + l4];
    float m_run = -INFINITY, s_run = 0.f;
    float4 acc = make_float4(0.f,0.f,0.f,0.f);
    int beg = g_rowptr[node], end = g_rowptr[node+1];

    for (int base=beg; base<end; base+=32){
        int cnt = min(32, end-base);
        {
            int s = 0; float4 ea = make_float4(0.f,0.f,0.f,0.f);
            if (lane < cnt){
                s  = g_esrc[base+lane];
                ea = *(const float4*)&g_eacsr[(size_t)(base+lane)*4];
            }
            sS[w][lane] = s; sEA[w][lane] = ea;
        }
        __syncwarp();
        int j = 0;
        for (; j+4<=cnt; j+=4){
            float4 xv[4]; float p[4];
            #pragma unroll
            for (int q=0;q<4;q++)
                xv[q] = ldh4(xl_buf + (size_t)sS[w][j+q]*HD + l4);
            #pragma unroll
            for (int q=0;q<4;q++)
                p[q] = edge_partial(xv[q], xr4, sEA[w][j+q], w0,w1,w2,w3, at4);
            #pragma unroll
            for (int o=16;o>0;o>>=1){
                #pragma unroll
                for (int q=0;q<4;q++) p[q] += __shfl_xor_sync(0xffffffffu, p[q], o);
            }
            #pragma unroll
            for (int q=0;q<4;q++){
                float nm = fmaxf(m_run, p[q]);
                float sc = __expf(m_run - nm);
                float wv = __expf(p[q] - nm);
                s_run = s_run*sc + wv;
                acc.x = acc.x*sc + wv*xv[q].x; acc.y = acc.y*sc + wv*xv[q].y;
                acc.z = acc.z*sc + wv*xv[q].z; acc.w = acc.w*sc + wv*xv[q].w;
                m_run = nm;
            }
        }
        for (; j<cnt; ++j){
            float4 xa = ldh4(xl_buf + (size_t)sS[w][j]*HD + l4);
            float pa = edge_partial(xa, xr4, sEA[w][j], w0,w1,w2,w3, at4);
            #pragma unroll
            for (int o=16;o>0;o>>=1) pa += __shfl_xor_sync(0xffffffffu, pa, o);
            float nm = fmaxf(m_run, pa);
            float sc = __expf(m_run - nm);
            float wv = __expf(pa - nm);
            s_run = s_run*sc + wv;
            acc.x = acc.x*sc + wv*xa.x; acc.y = acc.y*sc + wv*xa.y;
            acc.z = acc.z*sc + wv*xa.z; acc.w = acc.w*sc + wv*xa.w;
            m_run = nm;
        }
        __syncwarp();
    }
    float inv = 1.f/(s_run + 1e-16f);
    float4 o;
    o.x = fmaxf(acc.x*inv + b4.x, 0.f);
    o.y = fmaxf(acc.y*inv + b4.y, 0.f);
    o.z = fmaxf(acc.z*inv + b4.z, 0.f);
    o.w = fmaxf(acc.w*inv + b4.w, 0.f);
    *(float4*)&g_h[(size_t)node*HD + l4] = o;
}

// -------- final edge scorer: CSR-ordered, warp per dst node, fp16 gathers -----
__global__ void edge_score_csr(const __half* __restrict__ xl_buf,
                               const __half* __restrict__ xr_buf,
                               const float* __restrict__ Ws1c, const float* __restrict__ bs1,
                               const float* __restrict__ Ws2, const float* __restrict__ bs2,
                               float* __restrict__ out, int n, int ne){
    __shared__ __align__(16) float sWc[4*128];
    __shared__ __align__(16) float sB1[128];
    __shared__ __align__(16) float sW2[128];
    __shared__ int    sS[8][32];
    __shared__ int    sE[8][32];
    __shared__ float4 sEA[8][32];
    int t=threadIdx.x;
    for (int u=t;u<512;u+=256) sWc[u]=Ws1c[u];
    if (t<128){ sB1[t]=bs1[t]; sW2[t]=Ws2[t]; }
    __syncthreads();
    int lane=t&31, w=t>>5;
    int node = blockIdx.x*8 + w;
    if (node>=n) return;
    int l4=lane*4;
    float4 b  = ldh4(xr_buf + (size_t)node*HD + l4);
    float4 w0=*(const float4*)&sWc[0*HD+l4];
    float4 w1=*(const float4*)&sWc[1*HD+l4];
    float4 w2=*(const float4*)&sWc[2*HD+l4];
    float4 w3=*(const float4*)&sWc[3*HD+l4];
    float4 bb=*(const float4*)&sB1[l4];
    float4 wo=*(const float4*)&sW2[l4];
    float b2 = bs2[0];
    int beg = g_rowptr[node], end = g_rowptr[node+1];

    for (int base=beg; base<end; base+=32){
        int cnt = min(32, end-base);
        {
            int s=0, eid=ne; float4 ea = make_float4(0.f,0.f,0.f,0.f);
            if (lane<cnt){
                eid = g_eidx[base+lane];
                s   = g_esrc[base+lane];
                ea  = *(const float4*)&g_eacsr[(size_t)(base+lane)*4];
            }
            sS[w][lane]=s; sE[w][lane]=eid; sEA[w][lane]=ea;
        }
        __syncwarp();
        int j=0;
        for (; j+4<=cnt; j+=4){
            float p[4];
            #pragma unroll
            for (int q=0;q<4;q++){
                float4 aa = ldh4(xl_buf + (size_t)sS[w][j+q]*HD + l4);
                float4 ea = sEA[w][j+q];
                float hx = fmaxf(aa.x+b.x+ea.x*w0.x+ea.y*w1.x+ea.z*w2.x+ea.w*w3.x+bb.x, 0.f);
                float hy = fmaxf(aa.y+b.y+ea.x*w0.y+ea.y*w1.y+ea.z*w2.y+ea.w*w3.y+bb.y, 0.f);
                float hz = fmaxf(aa.z+b.z+ea.x*w0.z+ea.y*w1.z+ea.z*w2.z+ea.w*w3.z+bb.z, 0.f);
                float hw = fmaxf(aa.w+b.w+ea.x*w0.w+ea.y*w1.w+ea.z*w2.w+ea.w*w3.w+bb.w, 0.f);
                p[q] = hx*wo.x + hy*wo.y + hz*wo.z + hw*wo.w;
            }
            #pragma unroll
            for (int o=16;o>0;o>>=1){
                #pragma unroll
                for (int q=0;q<4;q++) p[q] += __shfl_xor_sync(0xffffffffu, p[q], o);
            }
            if (lane==0){
                #pragma unroll
                for (int q=0;q<4;q++){
                    int eid = sE[w][j+q];
                    if (eid<ne) out[eid] = p[q] + b2;
                }
            }
        }
        for (; j<cnt; ++j){
            float4 aa = ldh4(xl_buf + (size_t)sS[w][j]*HD + l4);
            float4 ea = sEA[w][j];
            float hx = fmaxf(aa.x+b.x+ea.x*w0.x+ea.y*w1.x+ea.z*w2.x+ea.w*w3.x+bb.x, 0.f);
            float hy = fmaxf(aa.y+b.y+ea.x*w0.y+ea.y*w1.y+ea.z*w2.y+ea.w*w3.y+bb.y, 0.f);
            float hz = fmaxf(aa.z+b.z+ea.x*w0.z+ea.y*w1.z+ea.z*w2.z+ea.w*w3.z+bb.z, 0.f);
            float hw = fmaxf(aa.w+b.w+ea.x*w0.w+ea.y*w1.w+ea.z*w2.w+ea.w*w3.w+bb.w, 0.f);
            float pa = hx*wo.x + hy*wo.y + hz*wo.z + hw*wo.w;
            #pragma unroll
            for (int o=16;o>0;o>>=1) pa += __shfl_xor_sync(0xffffffffu, pa, o);
            int eid = sE[w][j];
            if (lane==0 && eid<ne) out[eid] = pa + b2;
        }
        __syncwarp();
    }
}

// -----------------------------------------------------------------------------
extern "C" void kernel_launch(void* const* d_in, const int* in_sizes, int n_in,
                              void* d_out, int out_size) {
    const float* x        = (const float*)d_in[0];
    const float* edge_attr= (const float*)d_in[1];
    const float* Wj   = (const float*)d_in[2];
    const float* bj   = (const float*)d_in[3];
    const float* Wrt  = (const float*)d_in[4];
    const float* brt  = (const float*)d_in[5];
    const float* c1_Wl  = (const float*)d_in[6];
    const float* c1_Wr  = (const float*)d_in[7];
    const float* c1_We  = (const float*)d_in[8];
    const float* c1_att = (const float*)d_in[9];
    const float* c1_b   = (const float*)d_in[10];
    const float* c2_Wl  = (const float*)d_in[11];
    const float* c2_Wr  = (const float*)d_in[12];
    const float* c2_We  = (const float*)d_in[13];
    const float* c2_att = (const float*)d_in[14];
    const float* c2_b   = (const float*)d_in[15];
    const float* Ws1  = (const float*)d_in[16];
    const float* bs1  = (const float*)d_in[17];
    const float* Ws2  = (const float*)d_in[18];
    const float* bs2  = (const float*)d_in[19];
    const int*   eidx = (const int*)d_in[20];

    int n  = in_sizes[0]/3;
    int ne = in_sizes[1]/4;
    const int* srcs = eidx;
    const int* dsts = eidx + ne;
    float* out = (float*)d_out;

    float *d_h;
    __half *d_xlA, *d_xrA, *d_xlB, *d_xrB;
    cudaGetSymbolAddress((void**)&d_h,   g_h);
    cudaGetSymbolAddress((void**)&d_xlA, g_xlA);
    cudaGetSymbolAddress((void**)&d_xrA, g_xrA);
    cudaGetSymbolAddress((void**)&d_xlB, g_xlB);
    cudaGetSymbolAddress((void**)&d_xrB, g_xrB);

    // max(half staging 104448, fp32 epilogue 128*264*4=135168)
    const int SMEM_GEMM = 128*264*4;   // 135168 bytes
    cudaFuncSetAttribute(gemm2_k<1>, cudaFuncAttributeMaxDynamicSharedMemorySize, SMEM_GEMM);
    cudaFuncSetAttribute(gemm2_k<0>, cudaFuncAttributeMaxDynamicSharedMemorySize, SMEM_GEMM);

    int gblocks = (n+127)/128;   // 391
    int nblk = DEG_PAD/1024;     // 49

    // R8 fork/join: prep overlaps gemm1 (validated win)
    cudaStream_t side = 0;
    cudaEvent_t evA = 0, evB = 0;
    bool forked = (cudaStreamCreateWithFlags(&side, cudaStreamNonBlocking) == cudaSuccess);
    if (forked &&
        (cudaEventCreateWithFlags(&evA, cudaEventDisableTiming) != cudaSuccess ||
         cudaEventCreateWithFlags(&evB, cudaEventDisableTiming) != cudaSuccess)) {
        forked = false;
    }
    cudaStream_t sp = forked ? side : (cudaStream_t)0;

    if (forked){
        cudaEventRecord(evA, 0);
        cudaStreamWaitEvent(side, evA, 0);
    }

    // ---- side stream: CSR build chain ----
    ea_stage1<<<512,256,0,sp>>>(edge_attr, ne, n);            // launch 1
    deg_hist<<<(ne/4+255)/256,256,0,sp>>>(dsts, ne);          // launch 2
    scan1_k<<<nblk,256,0,sp>>>();                             // launch 3

    // ---- main stream: layer-1 GEMM (launch 4 <- ncu) ----
    gemm2_k<1><<<gblocks,256,SMEM_GEMM>>>(x, Wj,bj, Wrt,brt, c1_Wl, c1_Wr, d_xlA, d_xrA, n);

    // ---- side stream: rest of CSR build ----
    mid_k<<<1,256,0,sp>>>(1.0f/(float)ne, nblk);
    scan3_k<<<nblk,256,0,sp>>>();
    scatter_k<<<(ne+n+255)/256,256,0,sp>>>(srcs, dsts, edge_attr, ne, n);

    if (forked){
        cudaEventRecord(evB, side);
        cudaStreamWaitEvent(0, evB, 0);
    }

    // ---- main stream: rest of the network ----
    gat_agg_k<<<(n+7)/8,256>>>(d_xlA, d_xrA, c1_We, c1_att, c1_b, n);

    gemm2_k<0><<<gblocks,256,SMEM_GEMM>>>(d_h, Wj,bj, Wrt,brt, c2_Wl, c2_Wr, d_xlB, d_xrB, n);
    gat_agg_k<<<(n+7)/8,256>>>(d_xlB, d_xrB, c2_We, c2_att, c2_b, n);

    gemm2_k<0><<<gblocks,256,SMEM_GEMM>>>(d_h, Wj,bj, Wrt,brt, Ws1, Ws1 + 128*HD, d_xlA, d_xrA, n);
    edge_score_csr<<<(n+7)/8,256>>>(d_xlA, d_xrA, Ws1 + 256*HD, bs1, Ws2, bs2, out, n, ne);
    // Streams/events intentionally not destroyed during capture (see R7 note).
}

// round 13
// speedup vs baseline: 1.4928x; 1.0009x over previous
#include <cuda_runtime.h>
#include <cuda_fp16.h>
#include <mma.h>
#include <math.h>

using namespace nvcuda;

#define N_MAX 50000
#define N_PAD 50048
#define DEG_PAD 50176          // 49 * 1024
#define E_MAX 800000
#define HD 128
#define NEG 0.2f

// ---------------- device scratch (no runtime allocation allowed) -------------
__device__ __align__(16) __half g_h  [N_PAD*HD];
__device__ __align__(16) __half g_xlA[N_PAD*HD];
__device__ __align__(16) __half g_xrA[N_PAD*HD];
__device__ __align__(16) __half g_xlB[N_PAD*HD];
__device__ __align__(16) __half g_xrB[N_PAD*HD];
__device__ __align__(16) int   g_deg[DEG_PAD];
__device__ __align__(16) int   g_rowptr[DEG_PAD+4];
__device__ __align__(16) int   g_cursor[DEG_PAD];
__device__ int   g_eidx[E_MAX+N_MAX];
__device__ int   g_esrc[E_MAX+N_MAX];
__device__ __align__(16) float g_eacsr[(E_MAX+N_MAX)*4];
__device__ __align__(16) float g_eamean[4];
__device__ float g_partial[512*4];
__device__ int   g_blk[64];

// half[4] -> float4 via one 8-byte load
__device__ __forceinline__ float4 ldh4(const __half* p){
    uint2 raw = *(const uint2*)p;
    __half2 h0 = *(__half2*)&raw.x;
    __half2 h1 = *(__half2*)&raw.y;
    float2 f0 = __half22float2(h0);
    float2 f1 = __half22float2(h1);
    return make_float4(f0.x, f0.y, f1.x, f1.y);
}
__device__ __forceinline__ float4 u2tof4(uint2 raw){
    __half2 h0 = *(__half2*)&raw.x;
    __half2 h1 = *(__half2*)&raw.y;
    float2 f0 = __half22float2(h0);
    float2 f1 = __half22float2(h1);
    return make_float4(f0.x, f0.y, f1.x, f1.y);
}
// float4 -> half[4] 8-byte pack
__device__ __forceinline__ uint2 f4toh4(float4 v){
    __half2 h0 = __floats2half2_rn(v.x, v.y);
    __half2 h1 = __floats2half2_rn(v.z, v.w);
    uint2 r;
    r.x = *(unsigned*)&h0;
    r.y = *(unsigned*)&h1;
    return r;
}

// ---------------- mean(edge_attr) + deg init (fused) -------------------------
__global__ void ea_stage1(const float* __restrict__ ea, int ne, int n) {
    int gid = blockIdx.x*blockDim.x + threadIdx.x;
    if (gid < DEG_PAD) g_deg[gid] = (gid < n) ? 1 : 0;
    float s0=0.f,s1=0.f,s2=0.f,s3=0.f;
    for (int e = gid; e < ne; e += gridDim.x*blockDim.x) {
        float4 v = *(const float4*)(ea + 4*e);
        s0+=v.x; s1+=v.y; s2+=v.z; s3+=v.w;
    }
    #pragma unroll
    for (int o=16;o>0;o>>=1){
        s0+=__shfl_xor_sync(0xffffffffu,s0,o);
        s1+=__shfl_xor_sync(0xffffffffu,s1,o);
        s2+=__shfl_xor_sync(0xffffffffu,s2,o);
        s3+=__shfl_xor_sync(0xffffffffu,s3,o);
    }
    __shared__ float sh[8][4];
    int w = threadIdx.x>>5, l = threadIdx.x&31;
    if (l==0){ sh[w][0]=s0; sh[w][1]=s1; sh[w][2]=s2; sh[w][3]=s3; }
    __syncthreads();
    if (threadIdx.x < 4){
        float t=0.f;
        #pragma unroll
        for (int i=0;i<8;i++) t+=sh[i][threadIdx.x];
        g_partial[blockIdx.x*4+threadIdx.x]=t;
    }
}

__global__ void mid_k(float invE, int nblk){
    __shared__ float sh[256];
    int t=threadIdx.x, c=t&3;
    float s=0.f;
    for (int r=t>>2; r<512; r+=64) s+=g_partial[r*4+c];
    sh[t]=s; __syncthreads();
    for (int o=128;o>=4;o>>=1){ if(t<o) sh[t]+=sh[t+o]; __syncthreads(); }
    if (t<4) g_eamean[t]=sh[t]*invE;
    __syncthreads();
    __shared__ int ws[2];
    if (t < 64){
        int lane=t&31, w=t>>5;
        int v = (t<nblk)? g_blk[t] : 0;
        int x = v;
        #pragma unroll
        for (int o=1;o<32;o<<=1){ int y=__shfl_up_sync(0xffffffffu,x,o); if(lane>=o) x+=y; }
        if (lane==31) ws[w]=x;
    }
    __syncthreads();
    if (t < 64){
        int lane=t&31, w=t>>5;
        int v = (t<nblk)? g_blk[t] : 0;
        int x = v;
        #pragma unroll
        for (int o=1;o<32;o<<=1){ int y=__shfl_up_sync(0xffffffffu,x,o); if(lane>=o) x+=y; }
        if (w==1) x += ws[0];
        if (t<nblk) g_blk[t] = x - v;
    }
}

// ---------------- CSR build ---------------------------------------------------
__global__ void deg_hist(const int* __restrict__ dsts, int ne){
    int i = (blockIdx.x*blockDim.x+threadIdx.x)*4;
    if (i+3 < ne){
        int4 d = *(const int4*)&dsts[i];
        atomicAdd(&g_deg[d.x],1); atomicAdd(&g_deg[d.y],1);
        atomicAdd(&g_deg[d.z],1); atomicAdd(&g_deg[d.w],1);
    } else {
        for (int k=i; k<ne; ++k) atomicAdd(&g_deg[dsts[k]],1);
    }
}

__global__ void scan1_k(){
    __shared__ int wsum[8];
    int t=threadIdx.x, lane=t&31, wid=t>>5;
    int i0 = blockIdx.x*1024 + t*4;
    int4 v = *(const int4*)&g_deg[i0];
    int s = v.x+v.y+v.z+v.w;
    int x = s;
    #pragma unroll
    for (int o=1;o<32;o<<=1){ int y=__shfl_up_sync(0xffffffffu,x,o); if(lane>=o) x+=y; }
    if (lane==31) wsum[wid]=x;
    __syncthreads();
    if (t==0){
        int r=0;
        #pragma unroll
        for (int i=0;i<8;i++){ int tv=wsum[i]; wsum[i]=r; r+=tv; }
        g_blk[blockIdx.x]=r;
    }
    __syncthreads();
    int ex = wsum[wid] + x - s;
    int4 rp; rp.x=ex; rp.y=ex+v.x; rp.z=rp.y+v.y; rp.w=rp.z+v.z;
    *(int4*)&g_rowptr[i0]=rp;
}

__global__ void scan3_k(){
    int off = g_blk[blockIdx.x];
    int i0 = blockIdx.x*1024 + threadIdx.x*4;
    int4 rp = *(const int4*)&g_rowptr[i0];
    rp.x+=off; rp.y+=off; rp.z+=off; rp.w+=off;
    *(int4*)&g_rowptr[i0]=rp;
    *(int4*)&g_cursor[i0]=rp;
}

__global__ void scatter_k(const int* __restrict__ srcs, const int* __restrict__ dsts,
                          const float* __restrict__ edge_attr, int ne, int n){
    int e = blockIdx.x*blockDim.x+threadIdx.x;
    if (e>=ne+n) return;
    int d, s; float4 ea;
    if (e<ne){ d = dsts[e]; s = srcs[e]; ea = *(const float4*)&edge_attr[(size_t)e*4]; }
    else     { d = s = e-ne; ea = *(const float4*)g_eamean; }
    int pos = atomicAdd(&g_cursor[d],1);
    g_eidx[pos]=e;
    g_esrc[pos]=s;
    *(float4*)&g_eacsr[(size_t)pos*4] = ea;
}

// ---------------- fp16 tensor-core GEMM: C1 = A@W1, C2 = A@W2 (fp16 out) -----
// BM=128 x BN=256 (two mats). 8 warps, warp tile 64x64, K=16 per MMA (8 steps).
// ENC=1: A from encoder(x, fp32). ENC=0: A already fp16 (g_h).
#define AS_STRIDE 136          // halves
#define BSH_STRIDE 272         // halves (two 128-col mats, 136 each)
template<int ENC>
__global__ __launch_bounds__(256,1)
void gemm2_k(const void* __restrict__ Ain,
             const float* __restrict__ Wj, const float* __restrict__ bj,
             const float* __restrict__ Wrt, const float* __restrict__ brt,
             const float* __restrict__ W1, const float* __restrict__ W2,
             __half* __restrict__ C1, __half* __restrict__ C2, int n)
{
    extern __shared__ char dsmc[];
    __half (*As)[AS_STRIDE]  = (__half(*)[AS_STRIDE])dsmc;                      // 34816 B
    __half (*Bs)[BSH_STRIDE] = (__half(*)[BSH_STRIDE])(dsmc + 128*AS_STRIDE*2); // 69632 B
    float  (*Cs)[264]        = (float(*)[264])dsmc;                             // epilogue reuse
    __shared__ float sx[128][4];
    int t = threadIdx.x;
    int rowbase = blockIdx.x*128;

    // ---- stage both weight mats as half: 8192 groups of 4 halves ----
    #pragma unroll
    for (int u=0; u<32; u++){
        int id = t + u*256;            // 0..8191
        int mat = id>>12;              // 0..1
        int rem = id&4095;
        int kk = rem>>5, c4 = (rem&31)<<2;
        const float* W = mat ? W2 : W1;
        float4 v = *(const float4*)&W[(size_t)kk*HD + c4];
        *(uint2*)&Bs[kk][mat*136 + c4] = f4toh4(v);
    }

    // ---- stage A tile as half ----
    if (ENC){
        const float* xsrc = (const float*)Ain;
        for (int u=t; u<384; u+=256){
            int rr=u/3, c=u%3; int gr=rowbase+rr;
            sx[rr][c] = (gr<n)? xsrc[gr*3+c] : 0.f;
        }
        __syncthreads();
        int k  = t & 127;
        int r0 = t >> 7;
        float wj0=Wj[k],  wj1=Wj[HD+k],  wj2=Wj[2*HD+k],  bj_=bj[k];
        float wr0=Wrt[k], wr1=Wrt[HD+k], wr2=Wrt[2*HD+k], br_=brt[k];
        int half_ = n>>1;
        #pragma unroll 8
        for (int i=0;i<64;i++){
            int r = r0 + 2*i;
            int gr = rowbase + r;
            float x0=sx[r][0], x1=sx[r][1], x2=sx[r][2];
            float vj = bj_ + x0*wj0 + x1*wj1 + x2*wj2;
            float vr = br_ + x0*wr0 + x1*wr1 + x2*wr2;
            float v  = (gr < half_) ? vj : vr;
            v = (gr < n) ? fmaxf(v, 0.f) : 0.f;
            As[r][k] = __float2half_rn(v);
        }
    } else {
        const __half* hsrc = (const __half*)Ain;
        #pragma unroll
        for (int u=0; u<8; u++){
            int id = t + u*256;        // 0..2047 groups of 8 halves
            int r = id>>4, c8 = (id&15)<<3;
            uint4 v = *(const uint4*)&hsrc[(size_t)(rowbase+r)*HD + c8];
            *(uint4*)&As[r][c8] = v;
        }
    }
    __syncthreads();

    int wid = t>>5;
    int wr  = wid&1;                    // rows wr*64..+64
    int wc  = wid>>1;                   // cols wc*64..+64 (of 256)
    int bcol = (wc>>1)*136 + (wc&1)*64;

    wmma::fragment<wmma::accumulator,16,16,16,float> c[4][4];
    #pragma unroll
    for (int i=0;i<4;i++)
        #pragma unroll
        for (int j=0;j<4;j++) wmma::fill_fragment(c[i][j], 0.f);

    #pragma unroll
    for (int ks=0; ks<8; ks++){
        int k0 = ks*16;
        wmma::fragment<wmma::matrix_a,16,16,16,__half,wmma::row_major> a[4];
        wmma::fragment<wmma::matrix_b,16,16,16,__half,wmma::row_major> b[4];
        #pragma unroll
        for (int i=0;i<4;i++)
            wmma::load_matrix_sync(a[i], &As[wr*64 + i*16][k0], AS_STRIDE);
        #pragma unroll
        for (int j=0;j<4;j++)
            wmma::load_matrix_sync(b[j], &Bs[k0][bcol + j*16], BSH_STRIDE);
        #pragma unroll
        for (int i=0;i<4;i++)
            #pragma unroll
            for (int j=0;j<4;j++)
                wmma::mma_sync(c[i][j], a[i], b[j], c[i][j]);
    }

    // ---- epilogue: fp32 accums -> smem -> fp16 global ----
    __syncthreads();
    #pragma unroll
    for (int i=0;i<4;i++)
        #pragma unroll
        for (int j=0;j<4;j++)
            wmma::store_matrix_sync(&Cs[wr*64 + i*16][(wc>>1)*132 + (wc&1)*64 + j*16],
                                    c[i][j], 264, wmma::mem_row_major);
    __syncthreads();
    #pragma unroll
    for (int u=0; u<64; u++){
        int id = t + u*256;          // 0..16383 half2 units
        int mat = id>>13;
        int rem = id&8191;
        int row = rem>>6;
        int c2  = (rem&63)<<1;
        float v0 = Cs[row][mat*132 + c2];
        float v1 = Cs[row][mat*132 + c2 + 1];
        __half2 hv = __floats2half2_rn(v0, v1);
        __half* Cm = mat ? C2 : C1;
        *(__half2*)&Cm[(size_t)(rowbase+row)*HD + c2] = hv;
    }
}

// -------- GATv2 aggregation: warp/node, fp16 gathers, 4-wide + grouped softmax
__device__ __forceinline__ float edge_partial(
    float4 xl, float4 xr, float4 ea,
    float4 w0, float4 w1, float4 w2, float4 w3, float4 at)
{
    float mx = xl.x + xr.x + ea.x*w0.x + ea.y*w1.x + ea.z*w2.x + ea.w*w3.x;
    float my = xl.y + xr.y + ea.x*w0.y + ea.y*w1.y + ea.z*w2.y + ea.w*w3.y;
    float mz = xl.z + xr.z + ea.x*w0.z + ea.y*w1.z + ea.z*w2.z + ea.w*w3.z;
    float mw = xl.w + xr.w + ea.x*w0.w + ea.y*w1.w + ea.z*w2.w + ea.w*w3.w;
    float lx = mx>0.f? mx : NEG*mx;
    float ly = my>0.f? my : NEG*my;
    float lz = mz>0.f? mz : NEG*mz;
    float lw = mw>0.f? mw : NEG*mw;
    return at.x*lx + at.y*ly + at.z*lz + at.w*lw;
}

__global__ void gat_agg_k(const __half* __restrict__ xl_buf,
                          const __half* __restrict__ xr_buf,
                          const float* __restrict__ We,
                          const float* __restrict__ att,
                          const float* __restrict__ bias,
                          int n){
    __shared__ __align__(16) float sWe[4*128];
    __shared__ __align__(16) float sAtt[128];
    __shared__ __align__(16) float sB[128];
    __shared__ int    sS[8][32];
    __shared__ float4 sEA[8][32];
    int t=threadIdx.x;
    for (int u=t; u<512; u+=256) sWe[u]=We[u];
    if (t<128){ sAtt[t]=att[t]; sB[t]=bias[t]; }
    __syncthreads();
    int lane = t&31, w = t>>5;
    int node = blockIdx.x*8 + w;
    if (node>=n) return;
    int l4 = lane*4;
    float4 xr4 = ldh4(xr_buf + (size_t)node*HD + l4);
    float4 at4 = *(const float4*)&sAtt[l4];
    float4 b4  = *(const float4*)&sB[l4];
    float4 w0 = *(const float4*)&sWe[0*HD + l4];
    float4 w1 = *(const float4*)&sWe[1*HD + l4];
    float4 w2 = *(const float4*)&sWe[2*HD + l4];
    float4 w3 = *(const float4*)&sWe[3*HD + l4];
    float m_run = -INFINITY, s_run = 0.f;
    float4 acc = make_float4(0.f,0.f,0.f,0.f);
    int beg = g_rowptr[node], end = g_rowptr[node+1];

    for (int base=beg; base<end; base+=32){
        int cnt = min(32, end-base);
        {
            int s = 0; float4 ea = make_float4(0.f,0.f,0.f,0.f);
            if (lane < cnt){
                s  = g_esrc[base+lane];
                ea = *(const float4*)&g_eacsr[(size_t)(base+lane)*4];
            }
            sS[w][lane] = s; sEA[w][lane] = ea;
        }
        __syncwarp();
        int j = 0;
        for (; j+4<=cnt; j+=4){
            float4 xv[4]; float p[4];
            #pragma unroll
            for (int q=0;q<4;q++)
                xv[q] = ldh4(xl_buf + (size_t)sS[w][j+q]*HD + l4);
            #pragma unroll
            for (int q=0;q<4;q++)
                p[q] = edge_partial(xv[q], xr4, sEA[w][j+q], w0,w1,w2,w3, at4);
            #pragma unroll
            for (int o=16;o>0;o>>=1){
                #pragma unroll
                for (int q=0;q<4;q++) p[q] += __shfl_xor_sync(0xffffffffu, p[q], o);
            }
            // grouped online-softmax update (one rescale per 4 edges)
            float gm = fmaxf(fmaxf(p[0],p[1]), fmaxf(p[2],p[3]));
            float nm = fmaxf(m_run, gm);
            float sc = __expf(m_run - nm);
            float ws = 0.f;
            float4 xs = make_float4(0.f,0.f,0.f,0.f);
            #pragma unroll
            for (int q=0;q<4;q++){
                float wv = __expf(p[q] - nm);
                ws += wv;
                xs.x += wv*xv[q].x; xs.y += wv*xv[q].y;
                xs.z += wv*xv[q].z; xs.w += wv*xv[q].w;
            }
            s_run = s_run*sc + ws;
            acc.x = acc.x*sc + xs.x; acc.y = acc.y*sc + xs.y;
            acc.z = acc.z*sc + xs.z; acc.w = acc.w*sc + xs.w;
            m_run = nm;
        }
        for (; j<cnt; ++j){
            float4 xa = ldh4(xl_buf + (size_t)sS[w][j]*HD + l4);
            float pa = edge_partial(xa, xr4, sEA[w][j], w0,w1,w2,w3, at4);
            #pragma unroll
            for (int o=16;o>0;o>>=1) pa += __shfl_xor_sync(0xffffffffu, pa, o);
            float nm = fmaxf(m_run, pa);
            float sc = __expf(m_run - nm);
            float wv = __expf(pa - nm);
            s_run = s_run*sc + wv;
            acc.x = acc.x*sc + wv*xa.x; acc.y = acc.y*sc + wv*xa.y;
            acc.z = acc.z*sc + wv*xa.z; acc.w = acc.w*sc + wv*xa.w;
            m_run = nm;
        }
        __syncwarp();
    }
    float inv = 1.f/(s_run + 1e-16f);
    float4 o;
    o.x = fmaxf(acc.x*inv + b4.x, 0.f);
    o.y = fmaxf(acc.y*inv + b4.y, 0.f);
    o.z = fmaxf(acc.z*inv + b4.z, 0.f);
    o.w = fmaxf(acc.w*inv + b4.w, 0.f);
    *(uint2*)&g_h[(size_t)node*HD + l4] = f4toh4(o);   // fp16 h
}

// -------- final edge scorer: CSR-ordered, 8-wide raw uint2 staging ------------
__global__ void edge_score_csr(const __half* __restrict__ xl_buf,
                               const __half* __restrict__ xr_buf,
                               const float* __restrict__ Ws1c, const float* __restrict__ bs1,
                               const float* __restrict__ Ws2, const float* __restrict__ bs2,
                               float* __restrict__ out, int n, int ne){
    __shared__ __align__(16) float sWc[4*128];
    __shared__ __align__(16) float sB1[128];
    __shared__ __align__(16) float sW2[128];
    __shared__ int    sS[8][32];
    __shared__ int    sE[8][32];
    __shared__ float4 sEA[8][32];
    int t=threadIdx.x;
    for (int u=t;u<512;u+=256) sWc[u]=Ws1c[u];
    if (t<128){ sB1[t]=bs1[t]; sW2[t]=Ws2[t]; }
    __syncthreads();
    int lane=t&31, w=t>>5;
    int node = blockIdx.x*8 + w;
    if (node>=n) return;
    int l4=lane*4;
    float4 b  = ldh4(xr_buf + (size_t)node*HD + l4);
    float4 w0=*(const float4*)&sWc[0*HD+l4];
    float4 w1=*(const float4*)&sWc[1*HD+l4];
    float4 w2=*(const float4*)&sWc[2*HD+l4];
    float4 w3=*(const float4*)&sWc[3*HD+l4];
    float4 bb=*(const float4*)&sB1[l4];
    float4 wo=*(const float4*)&sW2[l4];
    float b2 = bs2[0];
    int beg = g_rowptr[node], end = g_rowptr[node+1];

    for (int base=beg; base<end; base+=32){
        int cnt = min(32, end-base);
        {
            int s=0, eid=ne; float4 ea = make_float4(0.f,0.f,0.f,0.f);
            if (lane<cnt){
                eid = g_eidx[base+lane];
                s   = g_esrc[base+lane];
                ea  = *(const float4*)&g_eacsr[(size_t)(base+lane)*4];
            }
            sS[w][lane]=s; sE[w][lane]=eid; sEA[w][lane]=ea;
        }
        __syncwarp();
        int j=0;
        for (; j+8<=cnt; j+=8){
            uint2 raw[8]; float p[8];
            #pragma unroll
            for (int q=0;q<8;q++)
                raw[q] = *(const uint2*)(xl_buf + (size_t)sS[w][j+q]*HD + l4);
            #pragma unroll
            for (int q=0;q<8;q++){
                float4 aa = u2tof4(raw[q]);
                float4 ea = sEA[w][j+q];
                float hx = fmaxf(aa.x+b.x+ea.x*w0.x+ea.y*w1.x+ea.z*w2.x+ea.w*w3.x+bb.x, 0.f);
                float hy = fmaxf(aa.y+b.y+ea.x*w0.y+ea.y*w1.y+ea.z*w2.y+ea.w*w3.y+bb.y, 0.f);
                float hz = fmaxf(aa.z+b.z+ea.x*w0.z+ea.y*w1.z+ea.z*w2.z+ea.w*w3.z+bb.z, 0.f);
                float hw = fmaxf(aa.w+b.w+ea.x*w0.w+ea.y*w1.w+ea.z*w2.w+ea.w*w3.w+bb.w, 0.f);
                p[q] = hx*wo.x + hy*wo.y + hz*wo.z + hw*wo.w;
            }
            #pragma unroll
            for (int o=16;o>0;o>>=1){
                #pragma unroll
                for (int q=0;q<8;q++) p[q] += __shfl_xor_sync(0xffffffffu, p[q], o);
            }
            if (lane==0){
                #pragma unroll
                for (int q=0;q<8;q++){
                    int eid = sE[w][j+q];
                    if (eid<ne) out[eid] = p[q] + b2;
                }
            }
        }
        for (; j<cnt; ++j){
            float4 aa = ldh4(xl_buf + (size_t)sS[w][j]*HD + l4);
            float4 ea = sEA[w][j];
            float hx = fmaxf(aa.x+b.x+ea.x*w0.x+ea.y*w1.x+ea.z*w2.x+ea.w*w3.x+bb.x, 0.f);
            float hy = fmaxf(aa.y+b.y+ea.x*w0.y+ea.y*w1.y+ea.z*w2.y+ea.w*w3.y+bb.y, 0.f);
            float hz = fmaxf(aa.z+b.z+ea.x*w0.z+ea.y*w1.z+ea.z*w2.z+ea.w*w3.z+bb.z, 0.f);
            float hw = fmaxf(aa.w+b.w+ea.x*w0.w+ea.y*w1.w+ea.z*w2.w+ea.w*w3.w+bb.w, 0.f);
            float pa = hx*wo.x + hy*wo.y + hz*wo.z + hw*wo.w;
            #pragma unroll
            for (int o=16;o>0;o>>=1) pa += __shfl_xor_sync(0xffffffffu, pa, o);
            int eid = sE[w][j];
            if (lane==0 && eid<ne) out[eid] = pa + b2;
        }
        __syncwarp();
    }
}

// -----------------------------------------------------------------------------
extern "C" void kernel_launch(void* const* d_in, const int* in_sizes, int n_in,
                              void* d_out, int out_size) {
    const float* x        = (const float*)d_in[0];
    const float* edge_attr= (const float*)d_in[1];
    const float* Wj   = (const float*)d_in[2];
    const float* bj   = (const float*)d_in[3];
    const float* Wrt  = (const float*)d_in[4];
    const float* brt  = (const float*)d_in[5];
    const float* c1_Wl  = (const float*)d_in[6];
    const float* c1_Wr  = (const float*)d_in[7];
    const float* c1_We  = (const float*)d_in[8];
    const float* c1_att = (const float*)d_in[9];
    const float* c1_b   = (const float*)d_in[10];
    const float* c2_Wl  = (const float*)d_in[11];
    const float* c2_Wr  = (const float*)d_in[12];
    const float* c2_We  = (const float*)d_in[13];
    const float* c2_att = (const float*)d_in[14];
    const float* c2_b   = (const float*)d_in[15];
    const float* Ws1  = (const float*)d_in[16];
    const float* bs1  = (const float*)d_in[17];
    const float* Ws2  = (const float*)d_in[18];
    const float* bs2  = (const float*)d_in[19];
    const int*   eidx = (const int*)d_in[20];

    int n  = in_sizes[0]/3;
    int ne = in_sizes[1]/4;
    const int* srcs = eidx;
    const int* dsts = eidx + ne;
    float* out = (float*)d_out;

    __half *d_h, *d_xlA, *d_xrA, *d_xlB, *d_xrB;
    cudaGetSymbolAddress((void**)&d_h,   g_h);
    cudaGetSymbolAddress((void**)&d_xlA, g_xlA);
    cudaGetSymbolAddress((void**)&d_xrA, g_xrA);
    cudaGetSymbolAddress((void**)&d_xlB, g_xlB);
    cudaGetSymbolAddress((void**)&d_xrB, g_xrB);

    const int SMEM_GEMM = 128*264*4;   // 135168 bytes (epilogue fp32 reuse)
    cudaFuncSetAttribute(gemm2_k<1>, cudaFuncAttributeMaxDynamicSharedMemorySize, SMEM_GEMM);
    cudaFuncSetAttribute(gemm2_k<0>, cudaFuncAttributeMaxDynamicSharedMemorySize, SMEM_GEMM);

    int gblocks = (n+127)/128;   // 391
    int nblk = DEG_PAD/1024;     // 49

    // R8 fork/join: prep overlaps gemm1 (validated win)
    cudaStream_t side = 0;
    cudaEvent_t evA = 0, evB = 0;
    bool forked = (cudaStreamCreateWithFlags(&side, cudaStreamNonBlocking) == cudaSuccess);
    if (forked &&
        (cudaEventCreateWithFlags(&evA, cudaEventDisableTiming) != cudaSuccess ||
         cudaEventCreateWithFlags(&evB, cudaEventDisableTiming) != cudaSuccess)) {
        forked = false;
    }
    cudaStream_t sp = forked ? side : (cudaStream_t)0;

    if (forked){
        cudaEventRecord(evA, 0);
        cudaStreamWaitEvent(side, evA, 0);
    }

    // ---- side stream: CSR build chain ----
    ea_stage1<<<512,256,0,sp>>>(edge_attr, ne, n);            // launch 1
    deg_hist<<<(ne/4+255)/256,256,0,sp>>>(dsts, ne);          // launch 2
    scan1_k<<<nblk,256,0,sp>>>();                             // launch 3

    // ---- main stream: layer-1 GEMM (launch 4 <- ncu) ----
    gemm2_k<1><<<gblocks,256,SMEM_GEMM>>>(x, Wj,bj, Wrt,brt, c1_Wl, c1_Wr, d_xlA, d_xrA, n);

    // ---- side stream: rest of CSR build ----
    mid_k<<<1,256,0,sp>>>(1.0f/(float)ne, nblk);
    scan3_k<<<nblk,256,0,sp>>>();
    scatter_k<<<(ne+n+255)/256,256,0,sp>>>(srcs, dsts, edge_attr, ne, n);

    if (forked){
        cudaEventRecord(evB, side);
        cudaStreamWaitEvent(0, evB, 0);
    }

    // ---- main stream: rest of the network ----
    gat_agg_k<<<(n+7)/8,256>>>(d_xlA, d_xrA, c1_We, c1_att, c1_b, n);

    gemm2_k<0><<<gblocks,256,SMEM_GEMM>>>(d_h, Wj,bj, Wrt,brt, c2_Wl, c2_Wr, d_xlB, d_xrB, n);
    gat_agg_k<<<(n+7)/8,256>>>(d_xlB, d_xrB, c2_We, c2_att, c2_b, n);

    gemm2_k<0><<<gblocks,256,SMEM_GEMM>>>(d_h, Wj,bj, Wrt,brt, Ws1, Ws1 + 128*HD, d_xlA, d_xrA, n);
    edge_score_csr<<<(n+7)/8,256>>>(d_xlA, d_xrA, Ws1 + 256*HD, bs1, Ws2, bs2, out, n, ne);
    // Streams/events intentionally not destroyed during capture (see R7 note).
}

// round 14
// speedup vs baseline: 1.5860x; 1.0624x over previous
#include <cuda_runtime.h>
#include <cuda_fp16.h>
#include <mma.h>
#include <math.h>

using namespace nvcuda;

#define N_MAX 50000
#define N_PAD 50048
#define DEG_PAD 50176          // 49 * 1024
#define E_MAX 800000
#define HD 128
#define NEG 0.2f

// ---------------- device scratch (no runtime allocation allowed) -------------
__device__ __align__(16) __half g_h  [N_PAD*HD];
__device__ __align__(16) __half g_xlA[N_PAD*HD];
__device__ __align__(16) __half g_xrA[N_PAD*HD];
__device__ __align__(16) __half g_xlB[N_PAD*HD];
__device__ __align__(16) __half g_xrB[N_PAD*HD];
__device__ __align__(16) int   g_deg[DEG_PAD];
__device__ __align__(16) int   g_rowptr[DEG_PAD+4];
__device__ __align__(16) int   g_cursor[DEG_PAD];
__device__ int   g_eidx[E_MAX+N_MAX];
__device__ int   g_esrc[E_MAX+N_MAX];
__device__ __align__(16) __half g_ea16[(E_MAX+N_MAX)*4];
__device__ __align__(16) float g_eamean[4];
__device__ float g_partial[512*4];
__device__ int   g_blk[64];

// half[4] -> float4 via one 8-byte load
__device__ __forceinline__ float4 ldh4(const __half* p){
    uint2 raw = *(const uint2*)p;
    __half2 h0 = *(__half2*)&raw.x;
    __half2 h1 = *(__half2*)&raw.y;
    float2 f0 = __half22float2(h0);
    float2 f1 = __half22float2(h1);
    return make_float4(f0.x, f0.y, f1.x, f1.y);
}
__device__ __forceinline__ float4 u2tof4(uint2 raw){
    __half2 h0 = *(__half2*)&raw.x;
    __half2 h1 = *(__half2*)&raw.y;
    float2 f0 = __half22float2(h0);
    float2 f1 = __half22float2(h1);
    return make_float4(f0.x, f0.y, f1.x, f1.y);
}
// float4 -> half[4] 8-byte pack
__device__ __forceinline__ uint2 f4toh4(float4 v){
    __half2 h0 = __floats2half2_rn(v.x, v.y);
    __half2 h1 = __floats2half2_rn(v.z, v.w);
    uint2 r;
    r.x = *(unsigned*)&h0;
    r.y = *(unsigned*)&h1;
    return r;
}

// ---------------- mean(edge_attr) + deg init (fused) -------------------------
__global__ void ea_stage1(const float* __restrict__ ea, int ne, int n) {
    int gid = blockIdx.x*blockDim.x + threadIdx.x;
    if (gid < DEG_PAD) g_deg[gid] = (gid < n) ? 1 : 0;
    float s0=0.f,s1=0.f,s2=0.f,s3=0.f;
    for (int e = gid; e < ne; e += gridDim.x*blockDim.x) {
        float4 v = *(const float4*)(ea + 4*e);
        s0+=v.x; s1+=v.y; s2+=v.z; s3+=v.w;
    }
    #pragma unroll
    for (int o=16;o>0;o>>=1){
        s0+=__shfl_xor_sync(0xffffffffu,s0,o);
        s1+=__shfl_xor_sync(0xffffffffu,s1,o);
        s2+=__shfl_xor_sync(0xffffffffu,s2,o);
        s3+=__shfl_xor_sync(0xffffffffu,s3,o);
    }
    __shared__ float sh[8][4];
    int w = threadIdx.x>>5, l = threadIdx.x&31;
    if (l==0){ sh[w][0]=s0; sh[w][1]=s1; sh[w][2]=s2; sh[w][3]=s3; }
    __syncthreads();
    if (threadIdx.x < 4){
        float t=0.f;
        #pragma unroll
        for (int i=0;i<8;i++) t+=sh[i][threadIdx.x];
        g_partial[blockIdx.x*4+threadIdx.x]=t;
    }
}

__global__ void mid_k(float invE, int nblk){
    __shared__ float sh[256];
    int t=threadIdx.x, c=t&3;
    float s=0.f;
    for (int r=t>>2; r<512; r+=64) s+=g_partial[r*4+c];
    sh[t]=s; __syncthreads();
    for (int o=128;o>=4;o>>=1){ if(t<o) sh[t]+=sh[t+o]; __syncthreads(); }
    if (t<4) g_eamean[t]=sh[t]*invE;
    __syncthreads();
    __shared__ int ws[2];
    if (t < 64){
        int lane=t&31, w=t>>5;
        int v = (t<nblk)? g_blk[t] : 0;
        int x = v;
        #pragma unroll
        for (int o=1;o<32;o<<=1){ int y=__shfl_up_sync(0xffffffffu,x,o); if(lane>=o) x+=y; }
        if (lane==31) ws[w]=x;
    }
    __syncthreads();
    if (t < 64){
        int lane=t&31, w=t>>5;
        int v = (t<nblk)? g_blk[t] : 0;
        int x = v;
        #pragma unroll
        for (int o=1;o<32;o<<=1){ int y=__shfl_up_sync(0xffffffffu,x,o); if(lane>=o) x+=y; }
        if (w==1) x += ws[0];
        if (t<nblk) g_blk[t] = x - v;
    }
}

// ---------------- CSR build ---------------------------------------------------
__global__ void deg_hist(const int* __restrict__ dsts, int ne){
    int i = (blockIdx.x*blockDim.x+threadIdx.x)*4;
    if (i+3 < ne){
        int4 d = *(const int4*)&dsts[i];
        atomicAdd(&g_deg[d.x],1); atomicAdd(&g_deg[d.y],1);
        atomicAdd(&g_deg[d.z],1); atomicAdd(&g_deg[d.w],1);
    } else {
        for (int k=i; k<ne; ++k) atomicAdd(&g_deg[dsts[k]],1);
    }
}

__global__ void scan1_k(){
    __shared__ int wsum[8];
    int t=threadIdx.x, lane=t&31, wid=t>>5;
    int i0 = blockIdx.x*1024 + t*4;
    int4 v = *(const int4*)&g_deg[i0];
    int s = v.x+v.y+v.z+v.w;
    int x = s;
    #pragma unroll
    for (int o=1;o<32;o<<=1){ int y=__shfl_up_sync(0xffffffffu,x,o); if(lane>=o) x+=y; }
    if (lane==31) wsum[wid]=x;
    __syncthreads();
    if (t==0){
        int r=0;
        #pragma unroll
        for (int i=0;i<8;i++){ int tv=wsum[i]; wsum[i]=r; r+=tv; }
        g_blk[blockIdx.x]=r;
    }
    __syncthreads();
    int ex = wsum[wid] + x - s;
    int4 rp; rp.x=ex; rp.y=ex+v.x; rp.z=rp.y+v.y; rp.w=rp.z+v.z;
    *(int4*)&g_rowptr[i0]=rp;
}

__global__ void scan3_k(){
    int off = g_blk[blockIdx.x];
    int i0 = blockIdx.x*1024 + threadIdx.x*4;
    int4 rp = *(const int4*)&g_rowptr[i0];
    rp.x+=off; rp.y+=off; rp.z+=off; rp.w+=off;
    *(int4*)&g_rowptr[i0]=rp;
    *(int4*)&g_cursor[i0]=rp;
}

__global__ void scatter_k(const int* __restrict__ srcs, const int* __restrict__ dsts,
                          const float* __restrict__ edge_attr, int ne, int n){
    int e = blockIdx.x*blockDim.x+threadIdx.x;
    if (e>=ne+n) return;
    int d, s; float4 ea;
    if (e<ne){ d = dsts[e]; s = srcs[e]; ea = *(const float4*)&edge_attr[(size_t)e*4]; }
    else     { d = s = e-ne; ea = *(const float4*)g_eamean; }
    int pos = atomicAdd(&g_cursor[d],1);
    g_eidx[pos]=e;
    g_esrc[pos]=s;
    *(uint2*)&g_ea16[(size_t)pos*4] = f4toh4(ea);
}

// ---------------- fp16 tensor-core GEMM: C1 = A@W1, C2 = A@W2 (fp16 out) -----
#define AS_STRIDE 136          // halves
#define BSH_STRIDE 272         // halves (two 128-col mats, 136 each)
template<int ENC>
__global__ __launch_bounds__(256,1)
void gemm2_k(const void* __restrict__ Ain,
             const float* __restrict__ Wj, const float* __restrict__ bj,
             const float* __restrict__ Wrt, const float* __restrict__ brt,
             const float* __restrict__ W1, const float* __restrict__ W2,
             __half* __restrict__ C1, __half* __restrict__ C2, int n)
{
    extern __shared__ char dsmc[];
    __half (*As)[AS_STRIDE]  = (__half(*)[AS_STRIDE])dsmc;                      // 34816 B
    __half (*Bs)[BSH_STRIDE] = (__half(*)[BSH_STRIDE])(dsmc + 128*AS_STRIDE*2); // 69632 B
    float  (*Cs)[264]        = (float(*)[264])dsmc;                             // epilogue reuse
    __shared__ float sx[128][4];
    int t = threadIdx.x;
    int rowbase = blockIdx.x*128;

    #pragma unroll
    for (int u=0; u<32; u++){
        int id = t + u*256;            // 0..8191
        int mat = id>>12;              // 0..1
        int rem = id&4095;
        int kk = rem>>5, c4 = (rem&31)<<2;
        const float* W = mat ? W2 : W1;
        float4 v = *(const float4*)&W[(size_t)kk*HD + c4];
        *(uint2*)&Bs[kk][mat*136 + c4] = f4toh4(v);
    }

    if (ENC){
        const float* xsrc = (const float*)Ain;
        for (int u=t; u<384; u+=256){
            int rr=u/3, c=u%3; int gr=rowbase+rr;
            sx[rr][c] = (gr<n)? xsrc[gr*3+c] : 0.f;
        }
        __syncthreads();
        int k  = t & 127;
        int r0 = t >> 7;
        float wj0=Wj[k],  wj1=Wj[HD+k],  wj2=Wj[2*HD+k],  bj_=bj[k];
        float wr0=Wrt[k], wr1=Wrt[HD+k], wr2=Wrt[2*HD+k], br_=brt[k];
        int half_ = n>>1;
        #pragma unroll 8
        for (int i=0;i<64;i++){
            int r = r0 + 2*i;
            int gr = rowbase + r;
            float x0=sx[r][0], x1=sx[r][1], x2=sx[r][2];
            float vj = bj_ + x0*wj0 + x1*wj1 + x2*wj2;
            float vr = br_ + x0*wr0 + x1*wr1 + x2*wr2;
            float v  = (gr < half_) ? vj : vr;
            v = (gr < n) ? fmaxf(v, 0.f) : 0.f;
            As[r][k] = __float2half_rn(v);
        }
    } else {
        const __half* hsrc = (const __half*)Ain;
        #pragma unroll
        for (int u=0; u<8; u++){
            int id = t + u*256;        // 0..2047 groups of 8 halves
            int r = id>>4, c8 = (id&15)<<3;
            uint4 v = *(const uint4*)&hsrc[(size_t)(rowbase+r)*HD + c8];
            *(uint4*)&As[r][c8] = v;
        }
    }
    __syncthreads();

    int wid = t>>5;
    int wr  = wid&1;
    int wc  = wid>>1;
    int bcol = (wc>>1)*136 + (wc&1)*64;

    wmma::fragment<wmma::accumulator,16,16,16,float> c[4][4];
    #pragma unroll
    for (int i=0;i<4;i++)
        #pragma unroll
        for (int j=0;j<4;j++) wmma::fill_fragment(c[i][j], 0.f);

    #pragma unroll
    for (int ks=0; ks<8; ks++){
        int k0 = ks*16;
        wmma::fragment<wmma::matrix_a,16,16,16,__half,wmma::row_major> a[4];
        wmma::fragment<wmma::matrix_b,16,16,16,__half,wmma::row_major> b[4];
        #pragma unroll
        for (int i=0;i<4;i++)
            wmma::load_matrix_sync(a[i], &As[wr*64 + i*16][k0], AS_STRIDE);
        #pragma unroll
        for (int j=0;j<4;j++)
            wmma::load_matrix_sync(b[j], &Bs[k0][bcol + j*16], BSH_STRIDE);
        #pragma unroll
        for (int i=0;i<4;i++)
            #pragma unroll
            for (int j=0;j<4;j++)
                wmma::mma_sync(c[i][j], a[i], b[j], c[i][j]);
    }

    __syncthreads();
    #pragma unroll
    for (int i=0;i<4;i++)
        #pragma unroll
        for (int j=0;j<4;j++)
            wmma::store_matrix_sync(&Cs[wr*64 + i*16][(wc>>1)*132 + (wc&1)*64 + j*16],
                                    c[i][j], 264, wmma::mem_row_major);
    __syncthreads();
    #pragma unroll
    for (int u=0; u<64; u++){
        int id = t + u*256;          // 0..16383 half2 units
        int mat = id>>13;
        int rem = id&8191;
        int row = rem>>6;
        int c2  = (rem&63)<<1;
        float v0 = Cs[row][mat*132 + c2];
        float v1 = Cs[row][mat*132 + c2 + 1];
        __half2 hv = __floats2half2_rn(v0, v1);
        __half* Cm = mat ? C2 : C1;
        *(__half2*)&Cm[(size_t)(rowbase+row)*HD + c2] = hv;
    }
}

// -------- GATv2 aggregation: warp/node, fp16 payloads, direct exp -------------
__device__ __forceinline__ float edge_partial(
    float4 xl, float4 xr, float4 ea,
    float4 w0, float4 w1, float4 w2, float4 w3, float4 at)
{
    float mx = xl.x + xr.x + ea.x*w0.x + ea.y*w1.x + ea.z*w2.x + ea.w*w3.x;
    float my = xl.y + xr.y + ea.x*w0.y + ea.y*w1.y + ea.z*w2.y + ea.w*w3.y;
    float mz = xl.z + xr.z + ea.x*w0.z + ea.y*w1.z + ea.z*w2.z + ea.w*w3.z;
    float mw = xl.w + xr.w + ea.x*w0.w + ea.y*w1.w + ea.z*w2.w + ea.w*w3.w;
    float lx = mx>0.f? mx : NEG*mx;
    float ly = my>0.f? my : NEG*my;
    float lz = mz>0.f? mz : NEG*mz;
    float lw = mw>0.f? mw : NEG*mw;
    return at.x*lx + at.y*ly + at.z*lz + at.w*lw;
}

__global__ void gat_agg_k(const __half* __restrict__ xl_buf,
                          const __half* __restrict__ xr_buf,
                          const float* __restrict__ We,
                          const float* __restrict__ att,
                          const float* __restrict__ bias,
                          int n){
    __shared__ __align__(16) float sWe[4*128];
    __shared__ __align__(16) float sAtt[128];
    __shared__ __align__(16) float sB[128];
    __shared__ int   sS[8][32];
    __shared__ uint2 sEA[8][32];
    int t=threadIdx.x;
    for (int u=t; u<512; u+=256) sWe[u]=We[u];
    if (t<128){ sAtt[t]=att[t]; sB[t]=bias[t]; }
    __syncthreads();
    int lane = t&31, w = t>>5;
    int node = blockIdx.x*8 + w;
    if (node>=n) return;
    int l4 = lane*4;
    float4 xr4 = ldh4(xr_buf + (size_t)node*HD + l4);
    float4 at4 = *(const float4*)&sAtt[l4];
    float4 b4  = *(const float4*)&sB[l4];
    float4 w0 = *(const float4*)&sWe[0*HD + l4];
    float4 w1 = *(const float4*)&sWe[1*HD + l4];
    float4 w2 = *(const float4*)&sWe[2*HD + l4];
    float4 w3 = *(const float4*)&sWe[3*HD + l4];
    float s_run = 0.f;
    float4 acc = make_float4(0.f,0.f,0.f,0.f);
    int beg = g_rowptr[node], end = g_rowptr[node+1];

    for (int base=beg; base<end; base+=32){
        int cnt = min(32, end-base);
        {
            int s = 0; uint2 ea = make_uint2(0u,0u);
            if (lane < cnt){
                s  = g_esrc[base+lane];
                ea = *(const uint2*)&g_ea16[(size_t)(base+lane)*4];
            }
            sS[w][lane] = s; sEA[w][lane] = ea;
        }
        __syncwarp();
        int j = 0;
        for (; j+4<=cnt; j+=4){
            float4 xv[4]; float p[4];
            #pragma unroll
            for (int q=0;q<4;q++)
                xv[q] = ldh4(xl_buf + (size_t)sS[w][j+q]*HD + l4);
            #pragma unroll
            for (int q=0;q<4;q++)
                p[q] = edge_partial(xv[q], xr4, u2tof4(sEA[w][j+q]), w0,w1,w2,w3, at4);
            #pragma unroll
            for (int o=16;o>0;o>>=1){
                #pragma unroll
                for (int q=0;q<4;q++) p[q] += __shfl_xor_sync(0xffffffffu, p[q], o);
            }
            // direct exp (scores bounded ~|p|<10; softmax shift-invariant)
            #pragma unroll
            for (int q=0;q<4;q++){
                float wv = __expf(p[q]);
                s_run += wv;
                acc.x += wv*xv[q].x; acc.y += wv*xv[q].y;
                acc.z += wv*xv[q].z; acc.w += wv*xv[q].w;
            }
        }
        for (; j<cnt; ++j){
            float4 xa = ldh4(xl_buf + (size_t)sS[w][j]*HD + l4);
            float pa = edge_partial(xa, xr4, u2tof4(sEA[w][j]), w0,w1,w2,w3, at4);
            #pragma unroll
            for (int o=16;o>0;o>>=1) pa += __shfl_xor_sync(0xffffffffu, pa, o);
            float wv = __expf(pa);
            s_run += wv;
            acc.x += wv*xa.x; acc.y += wv*xa.y;
            acc.z += wv*xa.z; acc.w += wv*xa.w;
        }
        __syncwarp();
    }
    float inv = 1.f/(s_run + 1e-16f);
    float4 o;
    o.x = fmaxf(acc.x*inv + b4.x, 0.f);
    o.y = fmaxf(acc.y*inv + b4.y, 0.f);
    o.z = fmaxf(acc.z*inv + b4.z, 0.f);
    o.w = fmaxf(acc.w*inv + b4.w, 0.f);
    *(uint2*)&g_h[(size_t)node*HD + l4] = f4toh4(o);
}

// -------- final edge scorer: CSR-ordered, fp16 payloads, bias folded ----------
__global__ void edge_score_csr(const __half* __restrict__ xl_buf,
                               const __half* __restrict__ xr_buf,
                               const float* __restrict__ Ws1c, const float* __restrict__ bs1,
                               const float* __restrict__ Ws2, const float* __restrict__ bs2,
                               float* __restrict__ out, int n, int ne){
    __shared__ __align__(16) float sWc[4*128];
    __shared__ __align__(16) float sB1[128];
    __shared__ __align__(16) float sW2[128];
    __shared__ int   sS[8][32];
    __shared__ int   sE[8][32];
    __shared__ uint2 sEA[8][32];
    int t=threadIdx.x;
    for (int u=t;u<512;u+=256) sWc[u]=Ws1c[u];
    if (t<128){ sB1[t]=bs1[t]; sW2[t]=Ws2[t]; }
    __syncthreads();
    int lane=t&31, w=t>>5;
    int node = blockIdx.x*8 + w;
    if (node>=n) return;
    int l4=lane*4;
    float4 b  = ldh4(xr_buf + (size_t)node*HD + l4);
    float4 bb = *(const float4*)&sB1[l4];
    b.x += bb.x; b.y += bb.y; b.z += bb.z; b.w += bb.w;   // fold bs1 into dst term
    float4 w0=*(const float4*)&sWc[0*HD+l4];
    float4 w1=*(const float4*)&sWc[1*HD+l4];
    float4 w2=*(const float4*)&sWc[2*HD+l4];
    float4 w3=*(const float4*)&sWc[3*HD+l4];
    float4 wo=*(const float4*)&sW2[l4];
    float b2 = bs2[0];
    int beg = g_rowptr[node], end = g_rowptr[node+1];

    for (int base=beg; base<end; base+=32){
        int cnt = min(32, end-base);
        {
            int s=0, eid=ne; uint2 ea = make_uint2(0u,0u);
            if (lane<cnt){
                eid = g_eidx[base+lane];
                s   = g_esrc[base+lane];
                ea  = *(const uint2*)&g_ea16[(size_t)(base+lane)*4];
            }
            sS[w][lane]=s; sE[w][lane]=eid; sEA[w][lane]=ea;
        }
        __syncwarp();
        int j=0;
        for (; j+8<=cnt; j+=8){
            uint2 raw[8]; float p[8];
            #pragma unroll
            for (int q=0;q<8;q++)
                raw[q] = *(const uint2*)(xl_buf + (size_t)sS[w][j+q]*HD + l4);
            #pragma unroll
            for (int q=0;q<8;q++){
                float4 aa = u2tof4(raw[q]);
                float4 ea = u2tof4(sEA[w][j+q]);
                float hx = fmaxf(aa.x+b.x+ea.x*w0.x+ea.y*w1.x+ea.z*w2.x+ea.w*w3.x, 0.f);
                float hy = fmaxf(aa.y+b.y+ea.x*w0.y+ea.y*w1.y+ea.z*w2.y+ea.w*w3.y, 0.f);
                float hz = fmaxf(aa.z+b.z+ea.x*w0.z+ea.y*w1.z+ea.z*w2.z+ea.w*w3.z, 0.f);
                float hw = fmaxf(aa.w+b.w+ea.x*w0.w+ea.y*w1.w+ea.z*w2.w+ea.w*w3.w, 0.f);
                p[q] = hx*wo.x + hy*wo.y + hz*wo.z + hw*wo.w;
            }
            #pragma unroll
            for (int o=16;o>0;o>>=1){
                #pragma unroll
                for (int q=0;q<8;q++) p[q] += __shfl_xor_sync(0xffffffffu, p[q], o);
            }
            if (lane==0){
                #pragma unroll
                for (int q=0;q<8;q++){
                    int eid = sE[w][j+q];
                    if (eid<ne) out[eid] = p[q] + b2;
                }
            }
        }
        for (; j<cnt; ++j){
            float4 aa = ldh4(xl_buf + (size_t)sS[w][j]*HD + l4);
            float4 ea = u2tof4(sEA[w][j]);
            float hx = fmaxf(aa.x+b.x+ea.x*w0.x+ea.y*w1.x+ea.z*w2.x+ea.w*w3.x, 0.f);
            float hy = fmaxf(aa.y+b.y+ea.x*w0.y+ea.y*w1.y+ea.z*w2.y+ea.w*w3.y, 0.f);
            float hz = fmaxf(aa.z+b.z+ea.x*w0.z+ea.y*w1.z+ea.z*w2.z+ea.w*w3.z, 0.f);
            float hw = fmaxf(aa.w+b.w+ea.x*w0.w+ea.y*w1.w+ea.z*w2.w+ea.w*w3.w, 0.f);
            float pa = hx*wo.x + hy*wo.y + hz*wo.z + hw*wo.w;
            #pragma unroll
            for (int o=16;o>0;o>>=1) pa += __shfl_xor_sync(0xffffffffu, pa, o);
            int eid = sE[w][j];
            if (lane==0 && eid<ne) out[eid] = pa + b2;
        }
        __syncwarp();
    }
}

// -----------------------------------------------------------------------------
extern "C" void kernel_launch(void* const* d_in, const int* in_sizes, int n_in,
                              void* d_out, int out_size) {
    const float* x        = (const float*)d_in[0];
    const float* edge_attr= (const float*)d_in[1];
    const float* Wj   = (const float*)d_in[2];
    const float* bj   = (const float*)d_in[3];
    const float* Wrt  = (const float*)d_in[4];
    const float* brt  = (const float*)d_in[5];
    const float* c1_Wl  = (const float*)d_in[6];
    const float* c1_Wr  = (const float*)d_in[7];
    const float* c1_We  = (const float*)d_in[8];
    const float* c1_att = (const float*)d_in[9];
    const float* c1_b   = (const float*)d_in[10];
    const float* c2_Wl  = (const float*)d_in[11];
    const float* c2_Wr  = (const float*)d_in[12];
    const float* c2_We  = (const float*)d_in[13];
    const float* c2_att = (const float*)d_in[14];
    const float* c2_b   = (const float*)d_in[15];
    const float* Ws1  = (const float*)d_in[16];
    const float* bs1  = (const float*)d_in[17];
    const float* Ws2  = (const float*)d_in[18];
    const float* bs2  = (const float*)d_in[19];
    const int*   eidx = (const int*)d_in[20];

    int n  = in_sizes[0]/3;
    int ne = in_sizes[1]/4;
    const int* srcs = eidx;
    const int* dsts = eidx + ne;
    float* out = (float*)d_out;

    __half *d_h, *d_xlA, *d_xrA, *d_xlB, *d_xrB;
    cudaGetSymbolAddress((void**)&d_h,   g_h);
    cudaGetSymbolAddress((void**)&d_xlA, g_xlA);
    cudaGetSymbolAddress((void**)&d_xrA, g_xrA);
    cudaGetSymbolAddress((void**)&d_xlB, g_xlB);
    cudaGetSymbolAddress((void**)&d_xrB, g_xrB);

    const int SMEM_GEMM = 128*264*4;   // 135168 bytes (epilogue fp32 reuse)
    cudaFuncSetAttribute(gemm2_k<1>, cudaFuncAttributeMaxDynamicSharedMemorySize, SMEM_GEMM);
    cudaFuncSetAttribute(gemm2_k<0>, cudaFuncAttributeMaxDynamicSharedMemorySize, SMEM_GEMM);

    int gblocks = (n+127)/128;   // 391
    int nblk = DEG_PAD/1024;     // 49

    // R8 fork/join: prep overlaps gemm1 (validated win)
    cudaStream_t side = 0;
    cudaEvent_t evA = 0, evB = 0;
    bool forked = (cudaStreamCreateWithFlags(&side, cudaStreamNonBlocking) == cudaSuccess);
    if (forked &&
        (cudaEventCreateWithFlags(&evA, cudaEventDisableTiming) != cudaSuccess ||
         cudaEventCreateWithFlags(&evB, cudaEventDisableTiming) != cudaSuccess)) {
        forked = false;
    }
    cudaStream_t sp = forked ? side : (cudaStream_t)0;

    if (forked){
        cudaEventRecord(evA, 0);
        cudaStreamWaitEvent(side, evA, 0);
    }

    // ---- side stream: CSR build chain ----
    ea_stage1<<<512,256,0,sp>>>(edge_attr, ne, n);            // launch 1
    deg_hist<<<(ne/4+255)/256,256,0,sp>>>(dsts, ne);          // launch 2
    scan1_k<<<nblk,256,0,sp>>>();                             // launch 3

    // ---- main stream: layer-1 GEMM (launch 4 <- ncu) ----
    gemm2_k<1><<<gblocks,256,SMEM_GEMM>>>(x, Wj,bj, Wrt,brt, c1_Wl, c1_Wr, d_xlA, d_xrA, n);

    // ---- side stream: rest of CSR build ----
    mid_k<<<1,256,0,sp>>>(1.0f/(float)ne, nblk);
    scan3_k<<<nblk,256,0,sp>>>();
    scatter_k<<<(ne+n+255)/256,256,0,sp>>>(srcs, dsts, edge_attr, ne, n);

    if (forked){
        cudaEventRecord(evB, side);
        cudaStreamWaitEvent(0, evB, 0);
    }

    // ---- main stream: rest of the network ----
    gat_agg_k<<<(n+7)/8,256>>>(d_xlA, d_xrA, c1_We, c1_att, c1_b, n);

    gemm2_k<0><<<gblocks,256,SMEM_GEMM>>>(d_h, Wj,bj, Wrt,brt, c2_Wl, c2_Wr, d_xlB, d_xrB, n);
    gat_agg_k<<<(n+7)/8,256>>>(d_xlB, d_xrB, c2_We, c2_att, c2_b, n);

    gemm2_k<0><<<gblocks,256,SMEM_GEMM>>>(d_h, Wj,bj, Wrt,brt, Ws1, Ws1 + 128*HD, d_xlA, d_xrA, n);
    edge_score_csr<<<(n+7)/8,256>>>(d_xlA, d_xrA, Ws1 + 256*HD, bs1, Ws2, bs2, out, n, ne);
    // Streams/events intentionally not destroyed during capture (see R7 note).
}